// round 2
// baseline (speedup 1.0000x reference)
#include <cuda_runtime.h>
#include <math_constants.h>

// ---------------------------------------------------------------------------
// VQ-VAE forward: encoder (conv+BN+ReLU x3, 1x1 conv) -> VQ -> decoder
// (1x1 convT, convT+BN+ReLU x2, 3x3 conv). Output: [128,3,64,64] + 2 losses.
// VQ distance emulates the reference fp32 computation bit-closely:
//   d2 = fl(fl(zz + cc_j) - fl(2*dot_j)), dot_j = sequential-k fp32 FMA chain.
// ---------------------------------------------------------------------------

// Scratch buffers (device globals; allocation APIs are forbidden)
__device__ float g_a1[128 * 64 * 64 * 64];   // encoder act 1
__device__ float g_a2[128 * 128 * 32 * 32];
__device__ float g_a3[128 * 192 * 16 * 16];
__device__ float g_h4[128 * 256 * 16 * 16];  // pre-VQ latents
__device__ float g_hq[128 * 256 * 16 * 16];  // quantized latents
__device__ float g_d1[128 * 192 * 16 * 16];
__device__ float g_d2[128 * 128 * 32 * 32];
__device__ float g_d3[128 * 64 * 64 * 64];
__device__ float g_scale[256];
__device__ float g_shift[256];
__device__ float g_lossp[32768];
__device__ float g_cc[256];

// ---------------------------------------------------------------------------
// Direct convolution (gather), one thread per output element.
// in:  [N, Cin, Hin, Win], w: [Cout, Cin, K, K]
// ---------------------------------------------------------------------------
template <int K, int S, int P>
__global__ void conv2d_k(const float* __restrict__ in, const float* __restrict__ w,
                         const float* __restrict__ bias, float* __restrict__ out,
                         int N, int Cin, int Hin, int Win, int Cout, int Hout, int Wout)
{
    int idx = blockIdx.x * blockDim.x + threadIdx.x;
    int total = N * Cout * Hout * Wout;
    if (idx >= total) return;
    int ox = idx % Wout; int t = idx / Wout;
    int oy = t % Hout;   t /= Hout;
    int oc = t % Cout;   int n = t / Cout;

    float acc = bias[oc];
    const float* wb = w + (long)oc * Cin * K * K;
    const float* ib = in + (long)n * Cin * Hin * Win;
    for (int ic = 0; ic < Cin; ic++) {
        const float* ibc = ib + (long)ic * Hin * Win;
        const float* wbc = wb + ic * K * K;
#pragma unroll
        for (int ky = 0; ky < K; ky++) {
            int iy = oy * S - P + ky;
            if ((unsigned)iy >= (unsigned)Hin) continue;
#pragma unroll
            for (int kx = 0; kx < K; kx++) {
                int ix = ox * S - P + kx;
                if ((unsigned)ix >= (unsigned)Win) continue;
                acc += ibc[iy * Win + ix] * wbc[ky * K + kx];
            }
        }
    }
    out[idx] = acc;
}

// ---------------------------------------------------------------------------
// Transposed convolution (gather form). w: [Cin, Cout, K, K] (torch layout).
// ---------------------------------------------------------------------------
template <int K, int S, int P>
__global__ void convT_k(const float* __restrict__ in, const float* __restrict__ w,
                        const float* __restrict__ bias, float* __restrict__ out,
                        int N, int Cin, int Hin, int Win, int Cout, int Hout, int Wout)
{
    int idx = blockIdx.x * blockDim.x + threadIdx.x;
    int total = N * Cout * Hout * Wout;
    if (idx >= total) return;
    int ox = idx % Wout; int t = idx / Wout;
    int oy = t % Hout;   t /= Hout;
    int oc = t % Cout;   int n = t / Cout;

    float acc = bias[oc];
    for (int ic = 0; ic < Cin; ic++) {
        const float* ib = in + ((long)(n * Cin + ic)) * Hin * Win;
        const float* wb = w + ((long)(ic * Cout + oc)) * K * K;
#pragma unroll
        for (int ky = 0; ky < K; ky++) {
            int ty = oy + P - ky;
            if (ty < 0 || (ty % S) != 0) continue;
            int iy = ty / S;
            if (iy >= Hin) continue;
#pragma unroll
            for (int kx = 0; kx < K; kx++) {
                int tx = ox + P - kx;
                if (tx < 0 || (tx % S) != 0) continue;
                int ix = tx / S;
                if (ix >= Win) continue;
                acc += ib[iy * Win + ix] * wb[ky * K + kx];
            }
        }
    }
    out[idx] = acc;
}

// 1x1 conv: w [Cout, Cin]
__global__ void conv1x1_k(const float* __restrict__ in, const float* __restrict__ w,
                          const float* __restrict__ bias, float* __restrict__ out,
                          int N, int Cin, int HW, int Cout)
{
    int idx = blockIdx.x * blockDim.x + threadIdx.x;
    int total = N * Cout * HW;
    if (idx >= total) return;
    int hw = idx % HW; int t = idx / HW;
    int oc = t % Cout; int n = t / Cout;
    float acc = bias[oc];
    const float* ib = in + (long)n * Cin * HW + hw;
    const float* wb = w + (long)oc * Cin;
    for (int ic = 0; ic < Cin; ic++)
        acc += ib[(long)ic * HW] * wb[ic];
    out[idx] = acc;
}

// 1x1 transposed conv: w [Cin, Cout]
__global__ void convT1x1_k(const float* __restrict__ in, const float* __restrict__ w,
                           const float* __restrict__ bias, float* __restrict__ out,
                           int N, int Cin, int HW, int Cout)
{
    int idx = blockIdx.x * blockDim.x + threadIdx.x;
    int total = N * Cout * HW;
    if (idx >= total) return;
    int hw = idx % HW; int t = idx / HW;
    int oc = t % Cout; int n = t / Cout;
    float acc = bias[oc];
    const float* ib = in + (long)n * Cin * HW + hw;
    for (int ic = 0; ic < Cin; ic++)
        acc += ib[(long)ic * HW] * w[(long)ic * Cout + oc];
    out[idx] = acc;
}

// ---------------------------------------------------------------------------
// BatchNorm stats: one block per channel; deterministic tree reduction.
// ---------------------------------------------------------------------------
__global__ void bn_stats_k(const float* __restrict__ x, const float* __restrict__ g,
                           const float* __restrict__ be, float* __restrict__ scale,
                           float* __restrict__ shift, int C, int N, int HW)
{
    int c = blockIdx.x;
    int tid = threadIdx.x;
    float s = 0.f, ss = 0.f;
    for (int n = 0; n < N; n++) {
        const float* p = x + ((long)(n * C + c)) * HW;
        for (int r = tid; r < HW; r += blockDim.x) {
            float v = p[r];
            s += v; ss += v * v;
        }
    }
    __shared__ float sh1[1024];
    __shared__ float sh2[1024];
    sh1[tid] = s; sh2[tid] = ss;
    __syncthreads();
    for (int ofs = blockDim.x >> 1; ofs > 0; ofs >>= 1) {
        if (tid < ofs) { sh1[tid] += sh1[tid + ofs]; sh2[tid] += sh2[tid + ofs]; }
        __syncthreads();
    }
    if (tid == 0) {
        float cnt = (float)N * (float)HW;
        float m = sh1[0] / cnt;
        float var = sh2[0] / cnt - m * m;
        float sc = g[c] * rsqrtf(var + 1e-5f);
        scale[c] = sc;
        shift[c] = be[c] - m * sc;
    }
}

__global__ void bn_apply_relu_k(float* __restrict__ x, const float* __restrict__ scale,
                                const float* __restrict__ shift, int C, int HW, int total)
{
    int idx = blockIdx.x * blockDim.x + threadIdx.x;
    if (idx >= total) return;
    int c = (idx / HW) % C;
    float v = x[idx] * scale[c] + shift[c];
    x[idx] = v > 0.f ? v : 0.f;
}

// ---------------------------------------------------------------------------
// cc[j] = sum_d cb[j][d]^2 (fp64 accumulate, store fp32)
// ---------------------------------------------------------------------------
__global__ void cc_k(const float* __restrict__ cb, float* __restrict__ cc)
{
    int j = blockIdx.x * blockDim.x + threadIdx.x;
    if (j >= 256) return;
    double s = 0.0;
    const float* row = cb + (long)j * 256;
    for (int d = 0; d < 256; d++) {
        double v = (double)row[d];
        s += v * v;
    }
    cc[j] = (float)s;
}

// ---------------------------------------------------------------------------
// Vector quantization with reference-exact fp32 distance emulation.
// Block: 64 positions of one image quarter. 64 threads, thread = position.
// For each code j (ascending): dot = sequential fp32 FMA chain over d=0..255;
// d2 = (zz + cc[j]) - 2.0f*dot; argmin keeps first (lowest j) on ties.
// ---------------------------------------------------------------------------
__global__ void vq_exact_k(const float* __restrict__ h, const float* __restrict__ cb,
                           const float* __restrict__ cc, float* __restrict__ hq,
                           float* __restrict__ lossp)
{
    const int POS = 64;
    int b = blockIdx.x >> 2;
    int hw0 = (blockIdx.x & 3) * POS;
    int p = threadIdx.x;                 // 0..63

    __shared__ float zs[256 * POS];      // [d][p]
    __shared__ float cbs[8 * 256];       // 8-code chunk [q][d]
    __shared__ float ccs[8];

    // Load z tile: zs[d][p] = h[b, d, hw0+p]   (coalesced)
    const float* hb = h + (long)b * 256 * 256 + hw0;
    for (int d = 0; d < 256; d++)
        zs[d * POS + p] = hb[d * 256 + p];
    __syncthreads();

    // zz (accuracy non-critical: common offset, grid-rounding argument)
    float zz = 0.f;
    for (int d = 0; d < 256; d++) {
        float z = zs[d * POS + p];
        zz = fmaf(z, z, zz);
    }

    float best = CUDART_INF_F;
    int bj = 0;

    for (int jc = 0; jc < 256; jc += 8) {
        __syncthreads();
        for (int t = p; t < 8 * 256; t += POS)
            cbs[t] = cb[jc * 256 + t];
        if (p < 8) ccs[p] = cc[jc + p];
        __syncthreads();

        float acc[8];
#pragma unroll
        for (int q = 0; q < 8; q++) acc[q] = 0.f;

        for (int dc = 0; dc < 256; dc += 32) {
            float zreg[32];
#pragma unroll
            for (int d = 0; d < 32; d++)
                zreg[d] = zs[(dc + d) * POS + p];
#pragma unroll
            for (int q = 0; q < 8; q++) {
#pragma unroll
                for (int d = 0; d < 32; d++)
                    acc[q] = fmaf(zreg[d], cbs[q * 256 + dc + d], acc[q]);
            }
        }

#pragma unroll
        for (int q = 0; q < 8; q++) {
            float d2 = (zz + ccs[q]) - 2.0f * acc[q];
            if (d2 < best) { best = d2; bj = jc + q; }
        }
    }

    // Quantized output + per-position loss
    const float* crow = cb + (long)bj * 256;
    float* hqb = hq + (long)b * 256 * 256 + hw0;
    float l = 0.f;
    for (int d = 0; d < 256; d++) {
        float c = crow[d];
        hqb[d * 256 + p] = c;
        float diff = zs[d * POS + p] - c;
        l = fmaf(diff, diff, l);
    }
    lossp[b * 256 + hw0 + p] = l;
}

// Deterministic mean of 32768 per-position losses (fp64); write both losses.
__global__ void loss_reduce_k(const float* __restrict__ lossp, float* __restrict__ out2)
{
    int tid = threadIdx.x;
    double s = 0.0;
    for (int i = tid; i < 32768; i += 1024) s += (double)lossp[i];
    __shared__ double sh[1024];
    sh[tid] = s;
    __syncthreads();
    for (int ofs = 512; ofs > 0; ofs >>= 1) {
        if (tid < ofs) sh[tid] += sh[tid + ofs];
        __syncthreads();
    }
    if (tid == 0) {
        float m = (float)(sh[0] / 32768.0);
        out2[0] = m;  // loss_commit
        out2[1] = m;  // loss_code (forward-identical)
    }
}

// ---------------------------------------------------------------------------
static inline int gridFor(int total, int block) { return (total + block - 1) / block; }

extern "C" void kernel_launch(void* const* d_in, const int* in_sizes, int n_in,
                              void* d_out, int out_size)
{
    const float* x        = (const float*)d_in[0];
    const float* codebook = (const float*)d_in[1];
    const float* e_w1 = (const float*)d_in[2];  const float* e_b1 = (const float*)d_in[3];
    const float* e_g1 = (const float*)d_in[4];  const float* e_be1 = (const float*)d_in[5];
    const float* e_w2 = (const float*)d_in[6];  const float* e_b2 = (const float*)d_in[7];
    const float* e_g2 = (const float*)d_in[8];  const float* e_be2 = (const float*)d_in[9];
    const float* e_w3 = (const float*)d_in[10]; const float* e_b3 = (const float*)d_in[11];
    const float* e_g3 = (const float*)d_in[12]; const float* e_be3 = (const float*)d_in[13];
    const float* e_w4 = (const float*)d_in[14]; const float* e_b4 = (const float*)d_in[15];
    const float* d_w1 = (const float*)d_in[16]; const float* d_b1 = (const float*)d_in[17];
    const float* d_g1 = (const float*)d_in[18]; const float* d_be1 = (const float*)d_in[19];
    const float* d_w2 = (const float*)d_in[20]; const float* d_b2 = (const float*)d_in[21];
    const float* d_g2 = (const float*)d_in[22]; const float* d_be2 = (const float*)d_in[23];
    const float* d_w3 = (const float*)d_in[24]; const float* d_b3 = (const float*)d_in[25];
    const float* d_g3 = (const float*)d_in[26]; const float* d_be3 = (const float*)d_in[27];
    const float* d_w4 = (const float*)d_in[28]; const float* d_b4 = (const float*)d_in[29];

    float* out = (float*)d_out;

    float *a1, *a2, *a3, *h4, *hq, *b1, *b2, *b3, *scale, *shift, *lossp, *cc;
    cudaGetSymbolAddress((void**)&a1, g_a1);
    cudaGetSymbolAddress((void**)&a2, g_a2);
    cudaGetSymbolAddress((void**)&a3, g_a3);
    cudaGetSymbolAddress((void**)&h4, g_h4);
    cudaGetSymbolAddress((void**)&hq, g_hq);
    cudaGetSymbolAddress((void**)&b1, g_d1);
    cudaGetSymbolAddress((void**)&b2, g_d2);
    cudaGetSymbolAddress((void**)&b3, g_d3);
    cudaGetSymbolAddress((void**)&scale, g_scale);
    cudaGetSymbolAddress((void**)&shift, g_shift);
    cudaGetSymbolAddress((void**)&lossp, g_lossp);
    cudaGetSymbolAddress((void**)&cc, g_cc);

    const int N = 128;
    const int BLK = 256;

    // ---- encoder ----
    {
        int total = N * 64 * 64 * 64;
        conv2d_k<3, 1, 1><<<gridFor(total, BLK), BLK>>>(x, e_w1, e_b1, a1,
                                                        N, 3, 64, 64, 64, 64, 64);
        bn_stats_k<<<64, 1024>>>(a1, e_g1, e_be1, scale, shift, 64, N, 4096);
        bn_apply_relu_k<<<gridFor(total, BLK), BLK>>>(a1, scale, shift, 64, 4096, total);
    }
    {
        int total = N * 128 * 32 * 32;
        conv2d_k<4, 2, 1><<<gridFor(total, BLK), BLK>>>(a1, e_w2, e_b2, a2,
                                                        N, 64, 64, 64, 128, 32, 32);
        bn_stats_k<<<128, 1024>>>(a2, e_g2, e_be2, scale, shift, 128, N, 1024);
        bn_apply_relu_k<<<gridFor(total, BLK), BLK>>>(a2, scale, shift, 128, 1024, total);
    }
    {
        int total = N * 192 * 16 * 16;
        conv2d_k<4, 2, 1><<<gridFor(total, BLK), BLK>>>(a2, e_w3, e_b3, a3,
                                                        N, 128, 32, 32, 192, 16, 16);
        bn_stats_k<<<192, 1024>>>(a3, e_g3, e_be3, scale, shift, 192, N, 256);
        bn_apply_relu_k<<<gridFor(total, BLK), BLK>>>(a3, scale, shift, 192, 256, total);
    }
    {
        int total = N * 256 * 256;
        conv1x1_k<<<gridFor(total, BLK), BLK>>>(a3, e_w4, e_b4, h4, N, 192, 256, 256);
    }

    // ---- vector quantization ----
    cc_k<<<1, 256>>>(codebook, cc);
    vq_exact_k<<<512, 64>>>(h4, codebook, cc, hq, lossp);
    loss_reduce_k<<<1, 1024>>>(lossp, out + (out_size - 2));

    // ---- decoder ----
    {
        int total = N * 192 * 256;
        convT1x1_k<<<gridFor(total, BLK), BLK>>>(hq, d_w1, d_b1, b1, N, 256, 256, 192);
        bn_stats_k<<<192, 1024>>>(b1, d_g1, d_be1, scale, shift, 192, N, 256);
        bn_apply_relu_k<<<gridFor(total, BLK), BLK>>>(b1, scale, shift, 192, 256, total);
    }
    {
        int total = N * 128 * 32 * 32;
        convT_k<4, 2, 1><<<gridFor(total, BLK), BLK>>>(b1, d_w2, d_b2, b2,
                                                       N, 192, 16, 16, 128, 32, 32);
        bn_stats_k<<<128, 1024>>>(b2, d_g2, d_be2, scale, shift, 128, N, 1024);
        bn_apply_relu_k<<<gridFor(total, BLK), BLK>>>(b2, scale, shift, 128, 1024, total);
    }
    {
        int total = N * 64 * 64 * 64;
        convT_k<4, 2, 1><<<gridFor(total, BLK), BLK>>>(b2, d_w3, d_b3, b3,
                                                       N, 128, 32, 32, 64, 64, 64);
        bn_stats_k<<<64, 1024>>>(b3, d_g3, d_be3, scale, shift, 64, N, 4096);
        bn_apply_relu_k<<<gridFor(total, BLK), BLK>>>(b3, scale, shift, 64, 4096, total);
    }
    {
        int total = N * 3 * 64 * 64;
        conv2d_k<3, 1, 1><<<gridFor(total, BLK), BLK>>>(b3, d_w4, d_b4, out,
                                                        N, 64, 64, 64, 3, 64, 64);
    }
}

// round 3
// speedup vs baseline: 5.2121x; 5.2121x over previous
#include <cuda_runtime.h>
#include <math_constants.h>

typedef unsigned long long u64;

// ---------------------------------------------------------------------------
// packed fp32x2 helpers (sm_100+): 2 independent fp32 FMAs per instruction,
// identical per-lane IEEE fp32 semantics -> bit-identical chains vs scalar.
// ---------------------------------------------------------------------------
__device__ __forceinline__ u64 pk(float lo, float hi) {
    u64 r;
    asm("mov.b64 %0, {%1, %2};" : "=l"(r) : "f"(lo), "f"(hi));
    return r;
}
__device__ __forceinline__ void upk(u64 v, float& lo, float& hi) {
    asm("mov.b64 {%0, %1}, %2;" : "=f"(lo), "=f"(hi) : "l"(v));
}
__device__ __forceinline__ void fma2(u64& d, u64 a, u64 b) {
    asm("fma.rn.f32x2 %0, %1, %2, %0;" : "+l"(d) : "l"(a), "l"(b));
}

// Scratch buffers (device globals; allocation APIs are forbidden)
__device__ float g_a1[128 * 64 * 64 * 64];
__device__ float g_a2[128 * 128 * 32 * 32];
__device__ float g_a3[128 * 192 * 16 * 16];
__device__ float g_h4[128 * 256 * 16 * 16];
__device__ float g_hq[128 * 256 * 16 * 16];
__device__ float g_d1[128 * 192 * 16 * 16];
__device__ float g_d2[128 * 128 * 32 * 32];
__device__ float g_d3[128 * 64 * 64 * 64];
__device__ float g_scale[256];
__device__ float g_shift[256];
__device__ float g_lossp[32768];
__device__ float g_cc[256];

// ---------------------------------------------------------------------------
// Forward conv, register/smem tiled. Block: 64 oc x 128 px. Thread: 8 oc x 4 px.
// Weights staged in smem pre-paired {w,w}. Per-acc FMA chain order: bias first,
// then (ic, ky, kx) ascending — bit-identical to the naive round-2 kernel.
// ---------------------------------------------------------------------------
template <int K, int S, int P, int ICT>
__global__ void __launch_bounds__(256)
convf_k(const float* __restrict__ in, const float* __restrict__ w,
        const float* __restrict__ bias, float* __restrict__ out,
        int Cin, int Hin, int Win, int Cout, int Hout, int Wout,
        int wsh, int npx)
{
    const int KK = K * K;
    const int KP = (K == 3) ? 12 : 16;       // padded u64 slots per (ic,oc)
    __shared__ u64 ws2[ICT * 64 * ((K == 3) ? 12 : 16)];

    int n    = blockIdx.y;
    int pxt  = blockIdx.x % npx;
    int oct  = blockIdx.x / npx;
    int tid  = threadIdx.x;
    int g    = tid >> 5;
    int lane = tid & 31;
    int hw0  = pxt * 128 + lane * 4;
    int oy   = hw0 >> wsh;
    int ox0  = hw0 & (Wout - 1);
    int ocb  = oct * 64 + g * 8;

    const int US = 3 * S + K;
    int xbase = ox0 * S - P;

    u64 acc[8][2];
#pragma unroll
    for (int o = 0; o < 8; o++) {
        float b = bias[ocb + o];
        acc[o][0] = pk(b, b);
        acc[o][1] = pk(b, b);
    }

    long inb = (long)n * Cin * Hin * Win;

    for (int ic0 = 0; ic0 < Cin; ic0 += ICT) {
        __syncthreads();
        if (K == 3) {
            for (int i = tid; i < ICT * 64 * 12; i += 256) ws2[i] = 0ull;
            __syncthreads();
            for (int i = tid; i < ICT * 64 * 9; i += 256) {
                int kk = i % 9; int oc = (i / 9) % 64; int ic = i / (9 * 64);
                float v = w[((long)(oct * 64 + oc) * Cin + ic0 + ic) * 9 + kk];
                ws2[(ic * 64 + oc) * 12 + (kk / 3) * 4 + kk % 3] = pk(v, v);
            }
        } else {
            for (int i = tid; i < ICT * 64 * 16; i += 256) {
                int kk = i & 15; int oc = (i >> 4) & 63; int ic = i >> 10;
                float v = w[((long)(oct * 64 + oc) * Cin + ic0 + ic) * 16 + kk];
                ws2[(ic * 64 + oc) * 16 + kk] = pk(v, v);
            }
        }
        __syncthreads();

        for (int ic = 0; ic < ICT; ic++) {
            const float* ib = in + inb + (long)(ic0 + ic) * Hin * Win;
#pragma unroll
            for (int ky = 0; ky < K; ky++) {
                int iy = oy * S - P + ky;
                bool yv = (unsigned)iy < (unsigned)Hin;
                const float* rp = ib + iy * Win;
                float u[US];
#pragma unroll
                for (int t = 0; t < US; t++) {
                    int x = xbase + t;
                    u[t] = (yv && (unsigned)x < (unsigned)Win) ? rp[x] : 0.f;
                }
                u64 U0[K], U1[K];
#pragma unroll
                for (int kx = 0; kx < K; kx++) {
                    U0[kx] = pk(u[kx], u[kx + S]);
                    U1[kx] = pk(u[kx + 2 * S], u[kx + 3 * S]);
                }
#pragma unroll
                for (int o = 0; o < 8; o++) {
                    const u64* wb = ws2 + (ic * 64 + g * 8 + o) * KP + ky * 4;
                    if (K == 4) {
                        ulonglong2 w01 = ((const ulonglong2*)wb)[0];
                        ulonglong2 w23 = ((const ulonglong2*)wb)[1];
                        fma2(acc[o][0], U0[0], w01.x); fma2(acc[o][1], U1[0], w01.x);
                        fma2(acc[o][0], U0[1], w01.y); fma2(acc[o][1], U1[1], w01.y);
                        fma2(acc[o][0], U0[2], w23.x); fma2(acc[o][1], U1[2], w23.x);
                        fma2(acc[o][0], U0[3], w23.y); fma2(acc[o][1], U1[3], w23.y);
                    } else {
                        ulonglong2 w01 = ((const ulonglong2*)wb)[0];
                        u64 w2 = wb[2];
                        fma2(acc[o][0], U0[0], w01.x); fma2(acc[o][1], U1[0], w01.x);
                        fma2(acc[o][0], U0[1], w01.y); fma2(acc[o][1], U1[1], w01.y);
                        fma2(acc[o][0], U0[2], w2);    fma2(acc[o][1], U1[2], w2);
                    }
                }
            }
        }
    }

    long ob = ((long)n * Cout + ocb) * Hout * Wout + hw0;
#pragma unroll
    for (int o = 0; o < 8; o++) {
        float4 v;
        upk(acc[o][0], v.x, v.y);
        upk(acc[o][1], v.z, v.w);
        *(float4*)(out + ob + (long)o * Hout * Wout) = v;
    }
    (void)KK;
}

// ---------------------------------------------------------------------------
// Transposed conv k4 s2 p1 via parity decomposition. blockIdx.z = class (a,b).
// Each class is a uniform 2x2-tap conv on a subsampled output grid.
// Tap order per acc: (ky asc, kx asc) matching the naive gather loop.
// ---------------------------------------------------------------------------
template <int ICT>
__global__ void __launch_bounds__(256)
convt_k(const float* __restrict__ in, const float* __restrict__ w,
        const float* __restrict__ bias, float* __restrict__ out,
        int Cin, int Hin, int Win, int Cout, int wsh, int npx)
{
    __shared__ u64 ws2[ICT * 64 * 4];

    int n   = blockIdx.y;
    int cls = blockIdx.z;
    int a = cls >> 1, b = cls & 1;
    int pxt = blockIdx.x % npx;
    int oct = blockIdx.x / npx;
    int tid = threadIdx.x;
    int g = tid >> 5, lane = tid & 31;
    int shw = pxt * 128 + lane * 4;
    int sy  = shw >> wsh;
    int sx0 = shw & (Win - 1);
    int ocb = oct * 64 + g * 8;
    int Wout = 2 * Win;

    int iy0 = sy + a;
    int iy1 = sy + a - 1;
    bool y0v = iy0 < Hin;
    bool y1v = iy1 >= 0;

    u64 acc[8][2];
#pragma unroll
    for (int o = 0; o < 8; o++) {
        float bb = bias[ocb + o];
        acc[o][0] = pk(bb, bb);
        acc[o][1] = pk(bb, bb);
    }

    long inb = (long)n * Cin * Hin * Win;

    for (int ic0 = 0; ic0 < Cin; ic0 += ICT) {
        __syncthreads();
        for (int i = tid; i < ICT * 64 * 4; i += 256) {
            int tap = i & 3; int oc = (i >> 2) & 63; int ic = i >> 8;
            int ky = 1 - a + 2 * (tap >> 1);
            int kx = 1 - b + 2 * (tap & 1);
            float v = w[((long)(ic0 + ic) * Cout + oct * 64 + oc) * 16 + ky * 4 + kx];
            ws2[i] = pk(v, v);
        }
        __syncthreads();

        for (int ic = 0; ic < ICT; ic++) {
            const float* base = in + inb + (long)(ic0 + ic) * Hin * Win;
            const float* p0 = base + iy0 * Win;
            const float* p1 = base + iy1 * Win;
            float u0[5], u1[5];
#pragma unroll
            for (int t = 0; t < 5; t++) {
                int x = sx0 + b - 1 + t;
                bool xv = (unsigned)x < (unsigned)Win;
                u0[t] = (y0v && xv) ? p0[x] : 0.f;
                u1[t] = (y1v && xv) ? p1[x] : 0.f;
            }
            // tap (ty,tx): in x-index = j + 1 - tx into u_ty
            u64 A0 = pk(u0[1], u0[2]), A1 = pk(u0[3], u0[4]);   // (0,0)
            u64 B0 = pk(u0[0], u0[1]), B1 = pk(u0[2], u0[3]);   // (0,1)
            u64 C0 = pk(u1[1], u1[2]), C1 = pk(u1[3], u1[4]);   // (1,0)
            u64 D0 = pk(u1[0], u1[1]), D1 = pk(u1[2], u1[3]);   // (1,1)
#pragma unroll
            for (int o = 0; o < 8; o++) {
                const ulonglong2* wp = (const ulonglong2*)(ws2 + (ic * 64 + g * 8 + o) * 4);
                ulonglong2 t01 = wp[0];
                ulonglong2 t23 = wp[1];
                fma2(acc[o][0], A0, t01.x); fma2(acc[o][1], A1, t01.x);
                fma2(acc[o][0], B0, t01.y); fma2(acc[o][1], B1, t01.y);
                fma2(acc[o][0], C0, t23.x); fma2(acc[o][1], C1, t23.x);
                fma2(acc[o][0], D0, t23.y); fma2(acc[o][1], D1, t23.y);
            }
        }
    }

    int oy = 2 * sy + a;
    long ob = ((long)n * Cout + ocb) * (4 * Hin * Win) + (long)oy * Wout;
#pragma unroll
    for (int o = 0; o < 8; o++) {
        float f[4];
        upk(acc[o][0], f[0], f[1]);
        upk(acc[o][1], f[2], f[3]);
        float* op = out + ob + (long)o * 4 * Hin * Win;
#pragma unroll
        for (int j = 0; j < 4; j++)
            op[2 * (sx0 + j) + b] = f[j];
    }
}

// ---------------------------------------------------------------------------
// 1x1 conv / convT as GEMM. TRANS=false: w[oc][ic]; TRANS=true: w[ic][oc].
// ---------------------------------------------------------------------------
template <int ICT, bool TRANS>
__global__ void __launch_bounds__(256)
gemm1x1_k(const float* __restrict__ in, const float* __restrict__ w,
          const float* __restrict__ bias, float* __restrict__ out,
          int Cin, int HW, int Cout, int npx)
{
    __shared__ u64 ws2[ICT * 64];
    int n = blockIdx.y;
    int pxt = blockIdx.x % npx, oct = blockIdx.x / npx;
    int tid = threadIdx.x;
    int g = tid >> 5, lane = tid & 31;
    int hw0 = pxt * 128 + lane * 4;
    int ocb = oct * 64 + g * 8;

    u64 acc[8][2];
#pragma unroll
    for (int o = 0; o < 8; o++) {
        float b = bias[ocb + o];
        acc[o][0] = pk(b, b);
        acc[o][1] = pk(b, b);
    }

    long inb = (long)n * Cin * HW + hw0;

    for (int ic0 = 0; ic0 < Cin; ic0 += ICT) {
        __syncthreads();
        for (int i = tid; i < ICT * 64; i += 256) {
            int oc = i & 63, ic = i >> 6;
            float v = TRANS ? w[(long)(ic0 + ic) * Cout + oct * 64 + oc]
                            : w[(long)(oct * 64 + oc) * Cin + ic0 + ic];
            ws2[i] = pk(v, v);
        }
        __syncthreads();

        for (int ic = 0; ic < ICT; ic++) {
            float4 v = *(const float4*)(in + inb + (long)(ic0 + ic) * HW);
            u64 U0 = pk(v.x, v.y), U1 = pk(v.z, v.w);
            const ulonglong2* wp = (const ulonglong2*)(ws2 + ic * 64 + g * 8);
#pragma unroll
            for (int k = 0; k < 4; k++) {
                ulonglong2 ww = wp[k];
                fma2(acc[2 * k][0], U0, ww.x);     fma2(acc[2 * k][1], U1, ww.x);
                fma2(acc[2 * k + 1][0], U0, ww.y); fma2(acc[2 * k + 1][1], U1, ww.y);
            }
        }
    }

    long ob = ((long)n * Cout + ocb) * HW + hw0;
#pragma unroll
    for (int o = 0; o < 8; o++) {
        float4 v;
        upk(acc[o][0], v.x, v.y);
        upk(acc[o][1], v.z, v.w);
        *(float4*)(out + ob + (long)o * HW) = v;
    }
}

// ---------------------------------------------------------------------------
// Final conv 64 -> 3, k3 s1 p1, writes decoded image to d_out.
// ---------------------------------------------------------------------------
__global__ void __launch_bounds__(256)
convlast_k(const float* __restrict__ in, const float* __restrict__ w,
           const float* __restrict__ bias, float* __restrict__ out)
{
    __shared__ u64 ws2[64 * 3 * 12];
    int n = blockIdx.y;
    int pxt = blockIdx.x;
    int tid = threadIdx.x;
    int hw0 = pxt * 1024 + tid * 4;
    int oy = hw0 >> 6, ox0 = hw0 & 63;

    for (int i = tid; i < 64 * 3 * 12; i += 256) ws2[i] = 0ull;
    __syncthreads();
    for (int i = tid; i < 64 * 3 * 9; i += 256) {
        int kk = i % 9; int t = i / 9; int oc = t % 3; int ic = t / 3;
        float v = w[((long)oc * 64 + ic) * 9 + kk];
        ws2[((ic * 3 + oc) * 3 + kk / 3) * 4 + kk % 3] = pk(v, v);
    }
    __syncthreads();

    u64 acc[3][2];
#pragma unroll
    for (int o = 0; o < 3; o++) {
        float b = bias[o];
        acc[o][0] = pk(b, b);
        acc[o][1] = pk(b, b);
    }

    const float* ib = in + (long)n * 64 * 4096;
    for (int ic = 0; ic < 64; ic++) {
        const float* ibc = ib + (long)ic * 4096;
#pragma unroll
        for (int ky = 0; ky < 3; ky++) {
            int iy = oy - 1 + ky;
            bool yv = (unsigned)iy < 64u;
            const float* rp = ibc + iy * 64;
            float u[6];
#pragma unroll
            for (int t = 0; t < 6; t++) {
                int x = ox0 - 1 + t;
                u[t] = (yv && (unsigned)x < 64u) ? rp[x] : 0.f;
            }
            u64 U0[3], U1[3];
#pragma unroll
            for (int kx = 0; kx < 3; kx++) {
                U0[kx] = pk(u[kx], u[kx + 1]);
                U1[kx] = pk(u[kx + 2], u[kx + 3]);
            }
#pragma unroll
            for (int o = 0; o < 3; o++) {
                const u64* wb = ws2 + ((ic * 3 + o) * 3 + ky) * 4;
                ulonglong2 w01 = ((const ulonglong2*)wb)[0];
                u64 w2 = wb[2];
                fma2(acc[o][0], U0[0], w01.x); fma2(acc[o][1], U1[0], w01.x);
                fma2(acc[o][0], U0[1], w01.y); fma2(acc[o][1], U1[1], w01.y);
                fma2(acc[o][0], U0[2], w2);    fma2(acc[o][1], U1[2], w2);
            }
        }
    }

#pragma unroll
    for (int o = 0; o < 3; o++) {
        float4 v;
        upk(acc[o][0], v.x, v.y);
        upk(acc[o][1], v.z, v.w);
        *(float4*)(out + ((long)n * 3 + o) * 4096 + hw0) = v;
    }
}

// ---------------------------------------------------------------------------
// BatchNorm stats: UNCHANGED from round 2 (bit-identical scale/shift -> the
// encoder latents and VQ argmins stay bit-identical to the passing run).
// ---------------------------------------------------------------------------
__global__ void bn_stats_k(const float* __restrict__ x, const float* __restrict__ g,
                           const float* __restrict__ be, float* __restrict__ scale,
                           float* __restrict__ shift, int C, int N, int HW)
{
    int c = blockIdx.x;
    int tid = threadIdx.x;
    float s = 0.f, ss = 0.f;
    for (int n = 0; n < N; n++) {
        const float* p = x + ((long)(n * C + c)) * HW;
        for (int r = tid; r < HW; r += blockDim.x) {
            float v = p[r];
            s += v; ss += v * v;
        }
    }
    __shared__ float sh1[1024];
    __shared__ float sh2[1024];
    sh1[tid] = s; sh2[tid] = ss;
    __syncthreads();
    for (int ofs = blockDim.x >> 1; ofs > 0; ofs >>= 1) {
        if (tid < ofs) { sh1[tid] += sh1[tid + ofs]; sh2[tid] += sh2[tid + ofs]; }
        __syncthreads();
    }
    if (tid == 0) {
        float cnt = (float)N * (float)HW;
        float m = sh1[0] / cnt;
        float var = sh2[0] / cnt - m * m;
        float sc = g[c] * rsqrtf(var + 1e-5f);
        scale[c] = sc;
        shift[c] = be[c] - m * sc;
    }
}

// vectorized BN apply + ReLU (same per-element math: FMA then max)
__global__ void bn_apply4_k(float4* __restrict__ x, const float* __restrict__ scale,
                            const float* __restrict__ shift, int C, int hwsh, int total4)
{
    int i = blockIdx.x * blockDim.x + threadIdx.x;
    if (i >= total4) return;
    int c = (i >> hwsh) % C;
    float s = scale[c], t = shift[c];
    float4 v = x[i];
    v.x = fmaxf(fmaf(v.x, s, t), 0.f);
    v.y = fmaxf(fmaf(v.y, s, t), 0.f);
    v.z = fmaxf(fmaf(v.z, s, t), 0.f);
    v.w = fmaxf(fmaf(v.w, s, t), 0.f);
    x[i] = v;
}

// ---------------------------------------------------------------------------
// cc[j] = sum_d cb[j][d]^2 (fp64 accumulate, store fp32)  [unchanged]
// ---------------------------------------------------------------------------
__global__ void cc_k(const float* __restrict__ cb, float* __restrict__ cc)
{
    int j = blockIdx.x * blockDim.x + threadIdx.x;
    if (j >= 256) return;
    double s = 0.0;
    const float* row = cb + (long)j * 256;
    for (int d = 0; d < 256; d++) {
        double v = (double)row[d];
        s += v * v;
    }
    cc[j] = (float)s;
}

// ---------------------------------------------------------------------------
// Vector quantization with reference-exact fp32 distance emulation [unchanged]
// ---------------------------------------------------------------------------
__global__ void vq_exact_k(const float* __restrict__ h, const float* __restrict__ cb,
                           const float* __restrict__ cc, float* __restrict__ hq,
                           float* __restrict__ lossp)
{
    const int POS = 64;
    int b = blockIdx.x >> 2;
    int hw0 = (blockIdx.x & 3) * POS;
    int p = threadIdx.x;

    __shared__ float zs[256 * POS];
    __shared__ float cbs[8 * 256];
    __shared__ float ccs[8];

    const float* hb = h + (long)b * 256 * 256 + hw0;
    for (int d = 0; d < 256; d++)
        zs[d * POS + p] = hb[d * 256 + p];
    __syncthreads();

    float zz = 0.f;
    for (int d = 0; d < 256; d++) {
        float z = zs[d * POS + p];
        zz = fmaf(z, z, zz);
    }

    float best = CUDART_INF_F;
    int bj = 0;

    for (int jc = 0; jc < 256; jc += 8) {
        __syncthreads();
        for (int t = p; t < 8 * 256; t += POS)
            cbs[t] = cb[jc * 256 + t];
        if (p < 8) ccs[p] = cc[jc + p];
        __syncthreads();

        float acc[8];
#pragma unroll
        for (int q = 0; q < 8; q++) acc[q] = 0.f;

        for (int dc = 0; dc < 256; dc += 32) {
            float zreg[32];
#pragma unroll
            for (int d = 0; d < 32; d++)
                zreg[d] = zs[(dc + d) * POS + p];
#pragma unroll
            for (int q = 0; q < 8; q++) {
#pragma unroll
                for (int d = 0; d < 32; d++)
                    acc[q] = fmaf(zreg[d], cbs[q * 256 + dc + d], acc[q]);
            }
        }

#pragma unroll
        for (int q = 0; q < 8; q++) {
            float d2 = (zz + ccs[q]) - 2.0f * acc[q];
            if (d2 < best) { best = d2; bj = jc + q; }
        }
    }

    const float* crow = cb + (long)bj * 256;
    float* hqb = hq + (long)b * 256 * 256 + hw0;
    float l = 0.f;
    for (int d = 0; d < 256; d++) {
        float c = crow[d];
        hqb[d * 256 + p] = c;
        float diff = zs[d * POS + p] - c;
        l = fmaf(diff, diff, l);
    }
    lossp[b * 256 + hw0 + p] = l;
}

__global__ void loss_reduce_k(const float* __restrict__ lossp, float* __restrict__ out2)
{
    int tid = threadIdx.x;
    double s = 0.0;
    for (int i = tid; i < 32768; i += 1024) s += (double)lossp[i];
    __shared__ double sh[1024];
    sh[tid] = s;
    __syncthreads();
    for (int ofs = 512; ofs > 0; ofs >>= 1) {
        if (tid < ofs) sh[tid] += sh[tid + ofs];
        __syncthreads();
    }
    if (tid == 0) {
        float m = (float)(sh[0] / 32768.0);
        out2[0] = m;
        out2[1] = m;
    }
}

// ---------------------------------------------------------------------------
static inline int gridFor(int total, int block) { return (total + block - 1) / block; }

extern "C" void kernel_launch(void* const* d_in, const int* in_sizes, int n_in,
                              void* d_out, int out_size)
{
    const float* x        = (const float*)d_in[0];
    const float* codebook = (const float*)d_in[1];
    const float* e_w1 = (const float*)d_in[2];  const float* e_b1 = (const float*)d_in[3];
    const float* e_g1 = (const float*)d_in[4];  const float* e_be1 = (const float*)d_in[5];
    const float* e_w2 = (const float*)d_in[6];  const float* e_b2 = (const float*)d_in[7];
    const float* e_g2 = (const float*)d_in[8];  const float* e_be2 = (const float*)d_in[9];
    const float* e_w3 = (const float*)d_in[10]; const float* e_b3 = (const float*)d_in[11];
    const float* e_g3 = (const float*)d_in[12]; const float* e_be3 = (const float*)d_in[13];
    const float* e_w4 = (const float*)d_in[14]; const float* e_b4 = (const float*)d_in[15];
    const float* d_w1 = (const float*)d_in[16]; const float* d_b1 = (const float*)d_in[17];
    const float* d_g1 = (const float*)d_in[18]; const float* d_be1 = (const float*)d_in[19];
    const float* d_w2 = (const float*)d_in[20]; const float* d_b2 = (const float*)d_in[21];
    const float* d_g2 = (const float*)d_in[22]; const float* d_be2 = (const float*)d_in[23];
    const float* d_w3 = (const float*)d_in[24]; const float* d_b3 = (const float*)d_in[25];
    const float* d_g3 = (const float*)d_in[26]; const float* d_be3 = (const float*)d_in[27];
    const float* d_w4 = (const float*)d_in[28]; const float* d_b4 = (const float*)d_in[29];

    float* out = (float*)d_out;

    float *a1, *a2, *a3, *h4, *hq, *b1, *b2, *b3, *scale, *shift, *lossp, *cc;
    cudaGetSymbolAddress((void**)&a1, g_a1);
    cudaGetSymbolAddress((void**)&a2, g_a2);
    cudaGetSymbolAddress((void**)&a3, g_a3);
    cudaGetSymbolAddress((void**)&h4, g_h4);
    cudaGetSymbolAddress((void**)&hq, g_hq);
    cudaGetSymbolAddress((void**)&b1, g_d1);
    cudaGetSymbolAddress((void**)&b2, g_d2);
    cudaGetSymbolAddress((void**)&b3, g_d3);
    cudaGetSymbolAddress((void**)&scale, g_scale);
    cudaGetSymbolAddress((void**)&shift, g_shift);
    cudaGetSymbolAddress((void**)&lossp, g_lossp);
    cudaGetSymbolAddress((void**)&cc, g_cc);

    const int N = 128;

    // ---- encoder ----
    // conv1: 3 -> 64, k3 s1 p1, 64x64 out (npx = 4096/128 = 32)
    convf_k<3, 1, 1, 3><<<dim3(32 * 1, N), 256>>>(x, e_w1, e_b1, a1,
                                                  3, 64, 64, 64, 64, 64, 6, 32);
    bn_stats_k<<<64, 1024>>>(a1, e_g1, e_be1, scale, shift, 64, N, 4096);
    bn_apply4_k<<<gridFor(N * 64 * 1024, 256), 256>>>((float4*)a1, scale, shift, 64, 10,
                                                      N * 64 * 1024);

    // conv2: 64 -> 128, k4 s2 p1, 32x32 out (npx = 8, oct = 2)
    convf_k<4, 2, 1, 8><<<dim3(8 * 2, N), 256>>>(a1, e_w2, e_b2, a2,
                                                 64, 64, 64, 128, 32, 32, 5, 8);
    bn_stats_k<<<128, 1024>>>(a2, e_g2, e_be2, scale, shift, 128, N, 1024);
    bn_apply4_k<<<gridFor(N * 128 * 256, 256), 256>>>((float4*)a2, scale, shift, 128, 8,
                                                      N * 128 * 256);

    // conv3: 128 -> 192, k4 s2 p1, 16x16 out (npx = 2, oct = 3)
    convf_k<4, 2, 1, 8><<<dim3(2 * 3, N), 256>>>(a2, e_w3, e_b3, a3,
                                                 128, 32, 32, 192, 16, 16, 4, 2);
    bn_stats_k<<<192, 1024>>>(a3, e_g3, e_be3, scale, shift, 192, N, 256);
    bn_apply4_k<<<gridFor(N * 192 * 64, 256), 256>>>((float4*)a3, scale, shift, 192, 6,
                                                     N * 192 * 64);

    // conv4: 192 -> 256, 1x1 (npx = 2, oct = 4)
    gemm1x1_k<32, false><<<dim3(2 * 4, N), 256>>>(a3, e_w4, e_b4, h4, 192, 256, 256, 2);

    // ---- vector quantization ----
    cc_k<<<1, 256>>>(codebook, cc);
    vq_exact_k<<<32768 / 64, 64>>>(h4, codebook, cc, hq, lossp);
    loss_reduce_k<<<1, 1024>>>(lossp, out + (out_size - 2));

    // ---- decoder ----
    // d1: convT 1x1, 256 -> 192 (npx = 2, oct = 3)
    gemm1x1_k<32, true><<<dim3(2 * 3, N), 256>>>(hq, d_w1, d_b1, b1, 256, 256, 192, 2);
    bn_stats_k<<<192, 1024>>>(b1, d_g1, d_be1, scale, shift, 192, N, 256);
    bn_apply4_k<<<gridFor(N * 192 * 64, 256), 256>>>((float4*)b1, scale, shift, 192, 6,
                                                     N * 192 * 64);

    // d2: convT 192 -> 128, k4 s2 p1, 16 -> 32 (sub 16x16: npx = 2, oct = 2)
    convt_k<16><<<dim3(2 * 2, N, 4), 256>>>(b1, d_w2, d_b2, b2, 192, 16, 16, 128, 4, 2);
    bn_stats_k<<<128, 1024>>>(b2, d_g2, d_be2, scale, shift, 128, N, 1024);
    bn_apply4_k<<<gridFor(N * 128 * 256, 256), 256>>>((float4*)b2, scale, shift, 128, 8,
                                                      N * 128 * 256);

    // d3: convT 128 -> 64, k4 s2 p1, 32 -> 64 (sub 32x32: npx = 8, oct = 1)
    convt_k<16><<<dim3(8 * 1, N, 4), 256>>>(b2, d_w3, d_b3, b3, 128, 32, 32, 64, 5, 8);
    bn_stats_k<<<64, 1024>>>(b3, d_g3, d_be3, scale, shift, 64, N, 4096);
    bn_apply4_k<<<gridFor(N * 64 * 1024, 256), 256>>>((float4*)b3, scale, shift, 64, 10,
                                                      N * 64 * 1024);

    // d4: conv 64 -> 3, k3 s1 p1 -> final output
    convlast_k<<<dim3(4, N), 256>>>(b3, d_w4, d_b4, out);
}

// round 4
// speedup vs baseline: 7.0358x; 1.3499x over previous
#include <cuda_runtime.h>
#include <math_constants.h>

typedef unsigned long long u64;

__device__ __forceinline__ u64 pk(float lo, float hi) {
    u64 r;
    asm("mov.b64 %0, {%1, %2};" : "=l"(r) : "f"(lo), "f"(hi));
    return r;
}
__device__ __forceinline__ void upk(u64 v, float& lo, float& hi) {
    asm("mov.b64 {%0, %1}, %2;" : "=f"(lo), "=f"(hi) : "l"(v));
}
__device__ __forceinline__ void fma2(u64& d, u64 a, u64 b) {
    asm("fma.rn.f32x2 %0, %1, %2, %0;" : "+l"(d) : "l"(a), "l"(b));
}

// Scratch buffers
__device__ float g_a1[128 * 64 * 64 * 64];
__device__ float g_a2[128 * 128 * 32 * 32];
__device__ float g_a3[128 * 192 * 16 * 16];
__device__ float g_h4[128 * 256 * 16 * 16];
__device__ float g_hq[128 * 256 * 16 * 16];
__device__ float g_d1[128 * 192 * 16 * 16];
__device__ float g_d2[128 * 128 * 32 * 32];
__device__ float g_d3[128 * 64 * 64 * 64];
__device__ float g_scale[256];
__device__ float g_shift[256];
__device__ float g_lossp[32768];
__device__ float g_cc[256];

// ---------------------------------------------------------------------------
// k4 s2 p1 forward conv, smem-staged + row-paired.
// Square images: Hin=Win=2*COLS, Hout=Wout=COLS. Block: 64 oc x 256 px
// (R=256/COLS rows x COLS cols). Thread: 8 oc x 4 row-pairs at one column.
// su pairs: {in[iy][x], in[iy+2][x]} split into even/odd x arrays.
// Chain per output: bias; (ic asc, ky asc, kx asc), zero-filled borders.
// ---------------------------------------------------------------------------
template <int COLS, int ICT>
__global__ void __launch_bounds__(256, 2)
convf2_k(const float* __restrict__ in, const float* __restrict__ w,
         const float* __restrict__ bias, float* __restrict__ out,
         int Cin, int Cout, int npx)
{
    const int R = 256 / COLS;
    const int NPAIR = 2 * R;
    const int TP = COLS + 2;
    const int HBLK = 32 / COLS;
    const int Win = 2 * COLS;
    const int Hin = 2 * COLS;

    __shared__ u64 sw[ICT * 64 * 16];
    __shared__ u64 su[ICT * NPAIR * 2 * TP];

    int n   = blockIdx.y;
    int pxt = blockIdx.x % npx;
    int oct = blockIdx.x / npx;
    int tid = threadIdx.x;
    int g   = tid >> 5;
    int lane = tid & 31;
    int c = lane % COLS;
    int h = lane / COLS;
    int oy0 = pxt * R;
    int ocb = oct * 64 + g * 8;

    u64 acc[8][4];
#pragma unroll
    for (int o = 0; o < 8; o++) {
        float b = bias[ocb + o];
#pragma unroll
        for (int t = 0; t < 4; t++) acc[o][t] = pk(b, b);
    }

    for (int ic0 = 0; ic0 < Cin; ic0 += ICT) {
        __syncthreads();
        // stage weights, pre-duplicated {w,w}
        for (int i = tid; i < ICT * 64 * 16; i += 256) {
            int kk = i & 15, oc = (i >> 4) & 63, icl = i >> 10;
            float v = w[((long)(oct * 64 + oc) * Cin + ic0 + icl) * 16 + kk];
            sw[(icl * 64 + oc) * 16 + kk] = pk(v, v);
        }
        // stage input row-pairs {row iy, row iy+2}, even/odd x split
        for (int i = tid; i < ICT * NPAIR * 2 * TP; i += 256) {
            int t = i % TP; int r = i / TP;
            int par = r & 1; r >>= 1;
            int j = r % NPAIR; int icl = r / NPAIR;
            int x = 2 * t - par;
            int iy = 2 * oy0 + j - 1;
            const float* bp = in + (long)(n * Cin + ic0 + icl) * (Hin * Win);
            bool xv = (unsigned)x < (unsigned)Win;
            float v0 = (xv && (unsigned)iy < (unsigned)Hin) ? bp[iy * Win + x] : 0.f;
            float v1 = (xv && (unsigned)(iy + 2) < (unsigned)Hin) ? bp[(iy + 2) * Win + x] : 0.f;
            su[i] = pk(v0, v1);
        }
        __syncthreads();

        for (int icl = 0; icl < ICT; icl++) {
#pragma unroll
            for (int ky = 0; ky < 4; ky++) {
                u64 q[4][4];   // [t][kx]
#pragma unroll
                for (int t = 0; t < 4; t++) {
                    int p = h + HBLK * t;
                    const u64* rowO = su + ((icl * NPAIR + (4 * p + ky)) * 2 + 1) * TP;
                    const u64* rowE = su + ((icl * NPAIR + (4 * p + ky)) * 2 + 0) * TP;
                    q[t][0] = rowO[c];     // x = 2c-1
                    q[t][1] = rowE[c];     // x = 2c
                    q[t][2] = rowO[c + 1]; // x = 2c+1
                    q[t][3] = rowE[c + 1]; // x = 2c+2
                }
#pragma unroll
                for (int o = 0; o < 8; o++) {
                    const u64* wb = sw + (icl * 64 + g * 8 + o) * 16 + ky * 4;
                    ulonglong2 w01 = ((const ulonglong2*)wb)[0];
                    ulonglong2 w23 = ((const ulonglong2*)wb)[1];
#pragma unroll
                    for (int t = 0; t < 4; t++) {
                        fma2(acc[o][t], q[t][0], w01.x);
                        fma2(acc[o][t], q[t][1], w01.y);
                        fma2(acc[o][t], q[t][2], w23.x);
                        fma2(acc[o][t], q[t][3], w23.y);
                    }
                }
            }
        }
    }

#pragma unroll
    for (int o = 0; o < 8; o++) {
#pragma unroll
        for (int t = 0; t < 4; t++) {
            int p = h + HBLK * t;
            int r0 = oy0 + 2 * p;
            float lo, hi;
            upk(acc[o][t], lo, hi);
            long ob = ((long)(n * Cout + ocb + o) * COLS + r0) * COLS + c;
            out[ob] = lo;
            out[ob + COLS] = hi;
        }
    }
}

// ---------------------------------------------------------------------------
// k4 s2 p1 transposed conv via parity classes, smem-staged + row-paired.
// blockIdx.z = class (a,b). Sub-grid = input grid (COLS x COLS).
// Pairs {row i, row i+1}. Per-acc tap order = (ky asc, kx asc) of the class.
// ---------------------------------------------------------------------------
template <int COLS, int ICT>
__global__ void __launch_bounds__(256, 2)
convt2_k(const float* __restrict__ in, const float* __restrict__ w,
         const float* __restrict__ bias, float* __restrict__ out,
         int Cin, int Cout, int npx)
{
    const int Rt = 256 / COLS;     // sub-rows per tile
    const int NPQ = Rt + 1;
    const int XP = COLS + 2;
    const int HBLK = 32 / COLS;
    const int Wout = 2 * COLS;

    __shared__ u64 swt[ICT * 64 * 4];
    __shared__ u64 qQ[ICT * NPQ * XP];

    int n   = blockIdx.y;
    int cls = blockIdx.z;
    int a = cls >> 1, b = cls & 1;
    int pxt = blockIdx.x % npx;
    int oct = blockIdx.x / npx;
    int tid = threadIdx.x;
    int g = tid >> 5, lane = tid & 31;
    int c = lane % COLS;
    int h = lane / COLS;
    int sy0 = pxt * Rt;
    int ocb = oct * 64 + g * 8;

    u64 acc[8][4];
#pragma unroll
    for (int o = 0; o < 8; o++) {
        float bb = bias[ocb + o];
#pragma unroll
        for (int t = 0; t < 4; t++) acc[o][t] = pk(bb, bb);
    }

    for (int ic0 = 0; ic0 < Cin; ic0 += ICT) {
        __syncthreads();
        for (int i = tid; i < ICT * 64 * 4; i += 256) {
            int tap = i & 3, oc = (i >> 2) & 63, icl = i >> 8;
            int ky = 1 - a + 2 * (tap >> 1);
            int kx = 1 - b + 2 * (tap & 1);
            float v = w[((long)(ic0 + icl) * Cout + oct * 64 + oc) * 16 + ky * 4 + kx];
            swt[i] = pk(v, v);
        }
        for (int i = tid; i < ICT * NPQ * XP; i += 256) {
            int tx = i % XP;
            int j = (i / XP) % NPQ;
            int icl = i / (XP * NPQ);
            int x = tx - 1;
            int r0 = sy0 - 1 + j;
            const float* bp = in + (long)(n * Cin + ic0 + icl) * (COLS * COLS);
            bool xv = (unsigned)x < (unsigned)COLS;
            float v0 = (xv && (unsigned)r0 < (unsigned)COLS) ? bp[r0 * COLS + x] : 0.f;
            float v1 = (xv && (unsigned)(r0 + 1) < (unsigned)COLS) ? bp[(r0 + 1) * COLS + x] : 0.f;
            qQ[i] = pk(v0, v1);
        }
        __syncthreads();

        for (int icl = 0; icl < ICT; icl++) {
            u64 q[2][4][2];   // [ty][t][txv]
#pragma unroll
            for (int ty = 0; ty < 2; ty++) {
#pragma unroll
                for (int t = 0; t < 4; t++) {
                    int p = h + HBLK * t;
                    int j = 2 * p + a + 1 - ty;
                    const u64* base = qQ + (icl * NPQ + j) * XP;
                    q[ty][t][0] = base[c + b + 1];  // x = c+b   (kx = 1-b)
                    q[ty][t][1] = base[c + b];      // x = c+b-1 (kx = 3-b)
                }
            }
#pragma unroll
            for (int o = 0; o < 8; o++) {
                const u64* wb = swt + (icl * 64 + g * 8 + o) * 4;
                ulonglong2 t01 = ((const ulonglong2*)wb)[0];
                ulonglong2 t23 = ((const ulonglong2*)wb)[1];
#pragma unroll
                for (int t = 0; t < 4; t++) {
                    fma2(acc[o][t], q[0][t][0], t01.x);
                    fma2(acc[o][t], q[0][t][1], t01.y);
                    fma2(acc[o][t], q[1][t][0], t23.x);
                    fma2(acc[o][t], q[1][t][1], t23.y);
                }
            }
        }
    }

#pragma unroll
    for (int o = 0; o < 8; o++) {
#pragma unroll
        for (int t = 0; t < 4; t++) {
            int p = h + HBLK * t;
            int s0 = sy0 + 2 * p;
            float lo, hi;
            upk(acc[o][t], lo, hi);
            long ob = ((long)(n * Cout + ocb + o) * Wout + 2 * s0 + a) * Wout + 2 * c + b;
            out[ob] = lo;
            out[ob + 2 * Wout] = hi;
        }
    }
}

// ---------------------------------------------------------------------------
// conv1 (3->64 k3 s1 p1) — small layer, round-3 kernel kept.
// ---------------------------------------------------------------------------
template <int K, int S, int P, int ICT>
__global__ void __launch_bounds__(256)
convf_k(const float* __restrict__ in, const float* __restrict__ w,
        const float* __restrict__ bias, float* __restrict__ out,
        int Cin, int Hin, int Win, int Cout, int Hout, int Wout,
        int wsh, int npx)
{
    const int KP = (K == 3) ? 12 : 16;
    __shared__ u64 ws2[ICT * 64 * ((K == 3) ? 12 : 16)];

    int n    = blockIdx.y;
    int pxt  = blockIdx.x % npx;
    int oct  = blockIdx.x / npx;
    int tid  = threadIdx.x;
    int g    = tid >> 5;
    int lane = tid & 31;
    int hw0  = pxt * 128 + lane * 4;
    int oy   = hw0 >> wsh;
    int ox0  = hw0 & (Wout - 1);
    int ocb  = oct * 64 + g * 8;

    const int US = 3 * S + K;
    int xbase = ox0 * S - P;

    u64 acc[8][2];
#pragma unroll
    for (int o = 0; o < 8; o++) {
        float b = bias[ocb + o];
        acc[o][0] = pk(b, b);
        acc[o][1] = pk(b, b);
    }

    long inb = (long)n * Cin * Hin * Win;

    for (int ic0 = 0; ic0 < Cin; ic0 += ICT) {
        __syncthreads();
        for (int i = tid; i < ICT * 64 * 12; i += 256) ws2[i] = 0ull;
        __syncthreads();
        for (int i = tid; i < ICT * 64 * 9; i += 256) {
            int kk = i % 9; int oc = (i / 9) % 64; int ic = i / (9 * 64);
            float v = w[((long)(oct * 64 + oc) * Cin + ic0 + ic) * 9 + kk];
            ws2[(ic * 64 + oc) * 12 + (kk / 3) * 4 + kk % 3] = pk(v, v);
        }
        __syncthreads();

        for (int ic = 0; ic < ICT; ic++) {
            const float* ib = in + inb + (long)(ic0 + ic) * Hin * Win;
#pragma unroll
            for (int ky = 0; ky < K; ky++) {
                int iy = oy * S - P + ky;
                bool yv = (unsigned)iy < (unsigned)Hin;
                const float* rp = ib + iy * Win;
                float u[US];
#pragma unroll
                for (int t = 0; t < US; t++) {
                    int x = xbase + t;
                    u[t] = (yv && (unsigned)x < (unsigned)Win) ? rp[x] : 0.f;
                }
                u64 U0[K], U1[K];
#pragma unroll
                for (int kx = 0; kx < K; kx++) {
                    U0[kx] = pk(u[kx], u[kx + S]);
                    U1[kx] = pk(u[kx + 2 * S], u[kx + 3 * S]);
                }
#pragma unroll
                for (int o = 0; o < 8; o++) {
                    const u64* wb = ws2 + (ic * 64 + g * 8 + o) * KP + ky * 4;
                    ulonglong2 w01 = ((const ulonglong2*)wb)[0];
                    u64 w2 = wb[2];
                    fma2(acc[o][0], U0[0], w01.x); fma2(acc[o][1], U1[0], w01.x);
                    fma2(acc[o][0], U0[1], w01.y); fma2(acc[o][1], U1[1], w01.y);
                    fma2(acc[o][0], U0[2], w2);    fma2(acc[o][1], U1[2], w2);
                }
            }
        }
    }

    long ob = ((long)n * Cout + ocb) * Hout * Wout + hw0;
#pragma unroll
    for (int o = 0; o < 8; o++) {
        float4 v;
        upk(acc[o][0], v.x, v.y);
        upk(acc[o][1], v.z, v.w);
        *(float4*)(out + ob + (long)o * Hout * Wout) = v;
    }
}

// ---------------------------------------------------------------------------
// 1x1 conv / convT as GEMM (round-3 kernel).
// ---------------------------------------------------------------------------
template <int ICT, bool TRANS>
__global__ void __launch_bounds__(256)
gemm1x1_k(const float* __restrict__ in, const float* __restrict__ w,
          const float* __restrict__ bias, float* __restrict__ out,
          int Cin, int HW, int Cout, int npx)
{
    __shared__ u64 ws2[ICT * 64];
    int n = blockIdx.y;
    int pxt = blockIdx.x % npx, oct = blockIdx.x / npx;
    int tid = threadIdx.x;
    int g = tid >> 5, lane = tid & 31;
    int hw0 = pxt * 128 + lane * 4;
    int ocb = oct * 64 + g * 8;

    u64 acc[8][2];
#pragma unroll
    for (int o = 0; o < 8; o++) {
        float b = bias[ocb + o];
        acc[o][0] = pk(b, b);
        acc[o][1] = pk(b, b);
    }

    long inb = (long)n * Cin * HW + hw0;

    for (int ic0 = 0; ic0 < Cin; ic0 += ICT) {
        __syncthreads();
        for (int i = tid; i < ICT * 64; i += 256) {
            int oc = i & 63, ic = i >> 6;
            float v = TRANS ? w[(long)(ic0 + ic) * Cout + oct * 64 + oc]
                            : w[(long)(oct * 64 + oc) * Cin + ic0 + ic];
            ws2[i] = pk(v, v);
        }
        __syncthreads();

        for (int ic = 0; ic < ICT; ic++) {
            float4 v = *(const float4*)(in + inb + (long)(ic0 + ic) * HW);
            u64 U0 = pk(v.x, v.y), U1 = pk(v.z, v.w);
            const ulonglong2* wp = (const ulonglong2*)(ws2 + ic * 64 + g * 8);
#pragma unroll
            for (int k = 0; k < 4; k++) {
                ulonglong2 ww = wp[k];
                fma2(acc[2 * k][0], U0, ww.x);     fma2(acc[2 * k][1], U1, ww.x);
                fma2(acc[2 * k + 1][0], U0, ww.y); fma2(acc[2 * k + 1][1], U1, ww.y);
            }
        }
    }

    long ob = ((long)n * Cout + ocb) * HW + hw0;
#pragma unroll
    for (int o = 0; o < 8; o++) {
        float4 v;
        upk(acc[o][0], v.x, v.y);
        upk(acc[o][1], v.z, v.w);
        *(float4*)(out + ob + (long)o * HW) = v;
    }
}

// ---------------------------------------------------------------------------
// Final conv 64 -> 3, k3 s1 p1 (round-3 kernel).
// ---------------------------------------------------------------------------
__global__ void __launch_bounds__(256)
convlast_k(const float* __restrict__ in, const float* __restrict__ w,
           const float* __restrict__ bias, float* __restrict__ out)
{
    __shared__ u64 ws2[64 * 3 * 12];
    int n = blockIdx.y;
    int pxt = blockIdx.x;
    int tid = threadIdx.x;
    int hw0 = pxt * 1024 + tid * 4;
    int oy = hw0 >> 6, ox0 = hw0 & 63;

    for (int i = tid; i < 64 * 3 * 12; i += 256) ws2[i] = 0ull;
    __syncthreads();
    for (int i = tid; i < 64 * 3 * 9; i += 256) {
        int kk = i % 9; int t = i / 9; int oc = t % 3; int ic = t / 3;
        float v = w[((long)oc * 64 + ic) * 9 + kk];
        ws2[((ic * 3 + oc) * 3 + kk / 3) * 4 + kk % 3] = pk(v, v);
    }
    __syncthreads();

    u64 acc[3][2];
#pragma unroll
    for (int o = 0; o < 3; o++) {
        float b = bias[o];
        acc[o][0] = pk(b, b);
        acc[o][1] = pk(b, b);
    }

    const float* ib = in + (long)n * 64 * 4096;
    for (int ic = 0; ic < 64; ic++) {
        const float* ibc = ib + (long)ic * 4096;
#pragma unroll
        for (int ky = 0; ky < 3; ky++) {
            int iy = oy - 1 + ky;
            bool yv = (unsigned)iy < 64u;
            const float* rp = ibc + iy * 64;
            float u[6];
#pragma unroll
            for (int t = 0; t < 6; t++) {
                int x = ox0 - 1 + t;
                u[t] = (yv && (unsigned)x < 64u) ? rp[x] : 0.f;
            }
            u64 U0[3], U1[3];
#pragma unroll
            for (int kx = 0; kx < 3; kx++) {
                U0[kx] = pk(u[kx], u[kx + 1]);
                U1[kx] = pk(u[kx + 2], u[kx + 3]);
            }
#pragma unroll
            for (int o = 0; o < 3; o++) {
                const u64* wb = ws2 + ((ic * 3 + o) * 3 + ky) * 4;
                ulonglong2 w01 = ((const ulonglong2*)wb)[0];
                u64 w2 = wb[2];
                fma2(acc[o][0], U0[0], w01.x); fma2(acc[o][1], U1[0], w01.x);
                fma2(acc[o][0], U0[1], w01.y); fma2(acc[o][1], U1[1], w01.y);
                fma2(acc[o][0], U0[2], w2);    fma2(acc[o][1], U1[2], w2);
            }
        }
    }

#pragma unroll
    for (int o = 0; o < 3; o++) {
        float4 v;
        upk(acc[o][0], v.x, v.y);
        upk(acc[o][1], v.z, v.w);
        *(float4*)(out + ((long)n * 3 + o) * 4096 + hw0) = v;
    }
}

// ---------------------------------------------------------------------------
// BatchNorm stats (unchanged — bit-identical scale/shift).
// ---------------------------------------------------------------------------
__global__ void bn_stats_k(const float* __restrict__ x, const float* __restrict__ g,
                           const float* __restrict__ be, float* __restrict__ scale,
                           float* __restrict__ shift, int C, int N, int HW)
{
    int c = blockIdx.x;
    int tid = threadIdx.x;
    float s = 0.f, ss = 0.f;
    for (int n = 0; n < N; n++) {
        const float* p = x + ((long)(n * C + c)) * HW;
        for (int r = tid; r < HW; r += blockDim.x) {
            float v = p[r];
            s += v; ss += v * v;
        }
    }
    __shared__ float sh1[1024];
    __shared__ float sh2[1024];
    sh1[tid] = s; sh2[tid] = ss;
    __syncthreads();
    for (int ofs = blockDim.x >> 1; ofs > 0; ofs >>= 1) {
        if (tid < ofs) { sh1[tid] += sh1[tid + ofs]; sh2[tid] += sh2[tid + ofs]; }
        __syncthreads();
    }
    if (tid == 0) {
        float cnt = (float)N * (float)HW;
        float m = sh1[0] / cnt;
        float var = sh2[0] / cnt - m * m;
        float sc = g[c] * rsqrtf(var + 1e-5f);
        scale[c] = sc;
        shift[c] = be[c] - m * sc;
    }
}

__global__ void bn_apply4_k(float4* __restrict__ x, const float* __restrict__ scale,
                            const float* __restrict__ shift, int C, int hwsh, int total4)
{
    int i = blockIdx.x * blockDim.x + threadIdx.x;
    if (i >= total4) return;
    int c = (i >> hwsh) % C;
    float s = scale[c], t = shift[c];
    float4 v = x[i];
    v.x = fmaxf(fmaf(v.x, s, t), 0.f);
    v.y = fmaxf(fmaf(v.y, s, t), 0.f);
    v.z = fmaxf(fmaf(v.z, s, t), 0.f);
    v.w = fmaxf(fmaf(v.w, s, t), 0.f);
    x[i] = v;
}

__global__ void cc_k(const float* __restrict__ cb, float* __restrict__ cc)
{
    int j = blockIdx.x * blockDim.x + threadIdx.x;
    if (j >= 256) return;
    double s = 0.0;
    const float* row = cb + (long)j * 256;
    for (int d = 0; d < 256; d++) {
        double v = (double)row[d];
        s += v * v;
    }
    cc[j] = (float)s;
}

// ---------------------------------------------------------------------------
// VQ with reference-exact fp32 distance emulation (unchanged).
// ---------------------------------------------------------------------------
__global__ void vq_exact_k(const float* __restrict__ h, const float* __restrict__ cb,
                           const float* __restrict__ cc, float* __restrict__ hq,
                           float* __restrict__ lossp)
{
    const int POS = 64;
    int b = blockIdx.x >> 2;
    int hw0 = (blockIdx.x & 3) * POS;
    int p = threadIdx.x;

    __shared__ float zs[256 * POS];
    __shared__ float cbs[8 * 256];
    __shared__ float ccs[8];

    const float* hb = h + (long)b * 256 * 256 + hw0;
    for (int d = 0; d < 256; d++)
        zs[d * POS + p] = hb[d * 256 + p];
    __syncthreads();

    float zz = 0.f;
    for (int d = 0; d < 256; d++) {
        float z = zs[d * POS + p];
        zz = fmaf(z, z, zz);
    }

    float best = CUDART_INF_F;
    int bj = 0;

    for (int jc = 0; jc < 256; jc += 8) {
        __syncthreads();
        for (int t = p; t < 8 * 256; t += POS)
            cbs[t] = cb[jc * 256 + t];
        if (p < 8) ccs[p] = cc[jc + p];
        __syncthreads();

        float acc[8];
#pragma unroll
        for (int q = 0; q < 8; q++) acc[q] = 0.f;

        for (int dc = 0; dc < 256; dc += 32) {
            float zreg[32];
#pragma unroll
            for (int d = 0; d < 32; d++)
                zreg[d] = zs[(dc + d) * POS + p];
#pragma unroll
            for (int q = 0; q < 8; q++) {
#pragma unroll
                for (int d = 0; d < 32; d++)
                    acc[q] = fmaf(zreg[d], cbs[q * 256 + dc + d], acc[q]);
            }
        }

#pragma unroll
        for (int q = 0; q < 8; q++) {
            float d2 = (zz + ccs[q]) - 2.0f * acc[q];
            if (d2 < best) { best = d2; bj = jc + q; }
        }
    }

    const float* crow = cb + (long)bj * 256;
    float* hqb = hq + (long)b * 256 * 256 + hw0;
    float l = 0.f;
    for (int d = 0; d < 256; d++) {
        float c = crow[d];
        hqb[d * 256 + p] = c;
        float diff = zs[d * POS + p] - c;
        l = fmaf(diff, diff, l);
    }
    lossp[b * 256 + hw0 + p] = l;
}

__global__ void loss_reduce_k(const float* __restrict__ lossp, float* __restrict__ out2)
{
    int tid = threadIdx.x;
    double s = 0.0;
    for (int i = tid; i < 32768; i += 1024) s += (double)lossp[i];
    __shared__ double sh[1024];
    sh[tid] = s;
    __syncthreads();
    for (int ofs = 512; ofs > 0; ofs >>= 1) {
        if (tid < ofs) sh[tid] += sh[tid + ofs];
        __syncthreads();
    }
    if (tid == 0) {
        float m = (float)(sh[0] / 32768.0);
        out2[0] = m;
        out2[1] = m;
    }
}

// ---------------------------------------------------------------------------
static inline int gridFor(int total, int block) { return (total + block - 1) / block; }

extern "C" void kernel_launch(void* const* d_in, const int* in_sizes, int n_in,
                              void* d_out, int out_size)
{
    const float* x        = (const float*)d_in[0];
    const float* codebook = (const float*)d_in[1];
    const float* e_w1 = (const float*)d_in[2];  const float* e_b1 = (const float*)d_in[3];
    const float* e_g1 = (const float*)d_in[4];  const float* e_be1 = (const float*)d_in[5];
    const float* e_w2 = (const float*)d_in[6];  const float* e_b2 = (const float*)d_in[7];
    const float* e_g2 = (const float*)d_in[8];  const float* e_be2 = (const float*)d_in[9];
    const float* e_w3 = (const float*)d_in[10]; const float* e_b3 = (const float*)d_in[11];
    const float* e_g3 = (const float*)d_in[12]; const float* e_be3 = (const float*)d_in[13];
    const float* e_w4 = (const float*)d_in[14]; const float* e_b4 = (const float*)d_in[15];
    const float* d_w1 = (const float*)d_in[16]; const float* d_b1 = (const float*)d_in[17];
    const float* d_g1 = (const float*)d_in[18]; const float* d_be1 = (const float*)d_in[19];
    const float* d_w2 = (const float*)d_in[20]; const float* d_b2 = (const float*)d_in[21];
    const float* d_g2 = (const float*)d_in[22]; const float* d_be2 = (const float*)d_in[23];
    const float* d_w3 = (const float*)d_in[24]; const float* d_b3 = (const float*)d_in[25];
    const float* d_g3 = (const float*)d_in[26]; const float* d_be3 = (const float*)d_in[27];
    const float* d_w4 = (const float*)d_in[28]; const float* d_b4 = (const float*)d_in[29];

    float* out = (float*)d_out;

    float *a1, *a2, *a3, *h4, *hq, *b1, *b2, *b3, *scale, *shift, *lossp, *cc;
    cudaGetSymbolAddress((void**)&a1, g_a1);
    cudaGetSymbolAddress((void**)&a2, g_a2);
    cudaGetSymbolAddress((void**)&a3, g_a3);
    cudaGetSymbolAddress((void**)&h4, g_h4);
    cudaGetSymbolAddress((void**)&hq, g_hq);
    cudaGetSymbolAddress((void**)&b1, g_d1);
    cudaGetSymbolAddress((void**)&b2, g_d2);
    cudaGetSymbolAddress((void**)&b3, g_d3);
    cudaGetSymbolAddress((void**)&scale, g_scale);
    cudaGetSymbolAddress((void**)&shift, g_shift);
    cudaGetSymbolAddress((void**)&lossp, g_lossp);
    cudaGetSymbolAddress((void**)&cc, g_cc);

    const int N = 128;

    // ---- encoder ----
    // conv1: 3 -> 64, k3 s1 p1
    convf_k<3, 1, 1, 3><<<dim3(32, N), 256>>>(x, e_w1, e_b1, a1,
                                              3, 64, 64, 64, 64, 64, 6, 32);
    bn_stats_k<<<64, 1024>>>(a1, e_g1, e_be1, scale, shift, 64, N, 4096);
    bn_apply4_k<<<gridFor(N * 64 * 1024, 256), 256>>>((float4*)a1, scale, shift, 64, 10,
                                                      N * 64 * 1024);

    // conv2: 64 -> 128, k4 s2 p1, 64->32  (COLS=32: npx=4, octiles=2)
    convf2_k<32, 2><<<dim3(4 * 2, N), 256>>>(a1, e_w2, e_b2, a2, 64, 128, 4);
    bn_stats_k<<<128, 1024>>>(a2, e_g2, e_be2, scale, shift, 128, N, 1024);
    bn_apply4_k<<<gridFor(N * 128 * 256, 256), 256>>>((float4*)a2, scale, shift, 128, 8,
                                                      N * 128 * 256);

    // conv3: 128 -> 192, k4 s2 p1, 32->16  (COLS=16: npx=1, octiles=3)
    convf2_k<16, 2><<<dim3(1 * 3, N), 256>>>(a2, e_w3, e_b3, a3, 128, 192, 1);
    bn_stats_k<<<192, 1024>>>(a3, e_g3, e_be3, scale, shift, 192, N, 256);
    bn_apply4_k<<<gridFor(N * 192 * 64, 256), 256>>>((float4*)a3, scale, shift, 192, 6,
                                                     N * 192 * 64);

    // conv4: 192 -> 256, 1x1
    gemm1x1_k<32, false><<<dim3(2 * 4, N), 256>>>(a3, e_w4, e_b4, h4, 192, 256, 256, 2);

    // ---- vector quantization ----
    cc_k<<<1, 256>>>(codebook, cc);
    vq_exact_k<<<512, 64>>>(h4, codebook, cc, hq, lossp);
    loss_reduce_k<<<1, 1024>>>(lossp, out + (out_size - 2));

    // ---- decoder ----
    // d1: convT 1x1, 256 -> 192
    gemm1x1_k<32, true><<<dim3(2 * 3, N), 256>>>(hq, d_w1, d_b1, b1, 256, 256, 192, 2);
    bn_stats_k<<<192, 1024>>>(b1, d_g1, d_be1, scale, shift, 192, N, 256);
    bn_apply4_k<<<gridFor(N * 192 * 64, 256), 256>>>((float4*)b1, scale, shift, 192, 6,
                                                     N * 192 * 64);

    // d2: convT 192 -> 128, 16->32  (COLS=16: npx=1, octiles=2, 4 classes)
    convt2_k<16, 4><<<dim3(1 * 2, N, 4), 256>>>(b1, d_w2, d_b2, b2, 192, 128, 1);
    bn_stats_k<<<128, 1024>>>(b2, d_g2, d_be2, scale, shift, 128, N, 1024);
    bn_apply4_k<<<gridFor(N * 128 * 256, 256), 256>>>((float4*)b2, scale, shift, 128, 8,
                                                      N * 128 * 256);

    // d3: convT 128 -> 64, 32->64  (COLS=32: npx=4, octiles=1, 4 classes)
    convt2_k<32, 4><<<dim3(4 * 1, N, 4), 256>>>(b2, d_w3, d_b3, b3, 128, 64, 4);
    bn_stats_k<<<64, 1024>>>(b3, d_g3, d_be3, scale, shift, 64, N, 4096);
    bn_apply4_k<<<gridFor(N * 64 * 1024, 256), 256>>>((float4*)b3, scale, shift, 64, 10,
                                                      N * 64 * 1024);

    // d4: conv 64 -> 3, k3 s1 p1 -> final output
    convlast_k<<<dim3(4, N), 256>>>(b3, d_w4, d_b4, out);
}

// round 6
// speedup vs baseline: 7.5234x; 1.0693x over previous
#include <cuda_runtime.h>
#include <math_constants.h>

typedef unsigned long long u64;

__device__ __forceinline__ u64 pk(float lo, float hi) {
    u64 r;
    asm("mov.b64 %0, {%1, %2};" : "=l"(r) : "f"(lo), "f"(hi));
    return r;
}
__device__ __forceinline__ void upk(u64 v, float& lo, float& hi) {
    asm("mov.b64 {%0, %1}, %2;" : "=f"(lo), "=f"(hi) : "l"(v));
}
__device__ __forceinline__ void fma2(u64& d, u64 a, u64 b) {
    asm("fma.rn.f32x2 %0, %1, %2, %0;" : "+l"(d) : "l"(a), "l"(b));
}

// Scratch buffers
__device__ float g_a1[128 * 64 * 64 * 64];
__device__ float g_a2[128 * 128 * 32 * 32];
__device__ float g_a3[128 * 192 * 16 * 16];
__device__ float g_h4[128 * 256 * 16 * 16];
__device__ float g_hq[128 * 256 * 16 * 16];
__device__ float g_d1[128 * 192 * 16 * 16];
__device__ float g_d2[128 * 128 * 32 * 32];
__device__ float g_d3[128 * 64 * 64 * 64];
__device__ float g_scale[256];
__device__ float g_shift[256];
__device__ float g_lossp[32768];
__device__ float g_cc[256];

// ---------------------------------------------------------------------------
// k4 s2 p1 forward conv, oc-packed fma2, raw-row smem, double-buffered.
// Output tile: 64 oc x RB rows x COLS cols. 8 warps = 4 oc-groups x 2 row-grps.
// Thread: 8 oc-pairs x RT rows at one column. acc u64 = {oc, oc+1}.
// Chain per output: bias; (ic asc, ky asc, kx asc); zero-filled borders.
// ---------------------------------------------------------------------------
template <int COLS, int RB, int ICT>
__global__ void __launch_bounds__(256, 2)
convf3_k(const float* __restrict__ in, const float* __restrict__ w,
         const float* __restrict__ bias, float* __restrict__ out,
         int Cin, int Cout, int npx)
{
    constexpr int HL = 32 / COLS;
    constexpr int RT = RB / (2 * HL);
    constexpr int SROWS = 2 * RB + 2;
    constexpr int SLOTW = 2 * COLS + 2;
    constexpr int SU = ICT * SROWS * SLOTW;
    constexpr int SW = ICT * 16 * 64;
    constexpr int BUF = SU + SW;
    extern __shared__ float smdyn[];

    const int Win = 2 * COLS, Hin = 2 * COLS;

    int n   = blockIdx.y;
    int pxt = blockIdx.x % npx;
    int oct = blockIdx.x / npx;
    int tid = threadIdx.x;
    int wrp = tid >> 5, lane = tid & 31;
    int og = wrp >> 1, rg = wrp & 1;
    int c  = lane % COLS, h = lane / COLS;
    int oy0 = pxt * RB;
    int ocb = oct * 64 + og * 16;
    int rl0 = rg * (RB / 2) + h * RT;

    u64 acc[8][RT];
#pragma unroll
    for (int j = 0; j < 8; j++) {
        u64 b2 = pk(bias[ocb + 2 * j], bias[ocb + 2 * j + 1]);
#pragma unroll
        for (int i = 0; i < RT; i++) acc[j][i] = b2;
    }

    auto stage = [&](int ic0, float* buf) {
        float* su = buf;
        float* swp = buf + SU;
        const float* ibase = in + ((long)n * Cin + ic0) * (long)(Hin * Win);
        for (int i = tid; i < SU; i += 256) {
            int s = i % SLOTW;
            int j = (i / SLOTW) % SROWS;
            int icl = i / (SLOTW * SROWS);
            int x = s - 1;
            int iy = 2 * oy0 - 1 + j;
            float v = 0.f;
            if ((unsigned)x < (unsigned)Win && (unsigned)iy < (unsigned)Hin)
                v = ibase[(long)icl * (Hin * Win) + iy * Win + x];
            su[i] = v;
        }
        const float* wbase = w + ((long)(oct * 64) * Cin + ic0) * 16;
        for (int i = tid; i < SW; i += 256) {
            int oc  = i & 63;
            int tk  = (i >> 6) & 15;
            int icl = i >> 10;
            swp[i] = wbase[((long)oc * Cin + icl) * 16 + tk];
        }
    };

    auto compute = [&](const float* buf) {
        const float* su = buf;
        const float* swp = buf + SU;
#pragma unroll 1
        for (int icl = 0; icl < ICT; icl++) {
#pragma unroll
            for (int ky = 0; ky < 4; ky++) {
                u64 qd[RT][4];
#pragma unroll
                for (int i = 0; i < RT; i++) {
                    const float* row = su + (icl * SROWS + 2 * (rl0 + i) + ky) * SLOTW + 2 * c;
                    float2 f01 = *(const float2*)(row);
                    float2 f23 = *(const float2*)(row + 2);
                    qd[i][0] = pk(f01.x, f01.x);
                    qd[i][1] = pk(f01.y, f01.y);
                    qd[i][2] = pk(f23.x, f23.x);
                    qd[i][3] = pk(f23.y, f23.y);
                }
#pragma unroll
                for (int kx = 0; kx < 4; kx++) {
                    const ulonglong2* wp =
                        (const ulonglong2*)(swp + (icl * 16 + ky * 4 + kx) * 64 + og * 16);
                    ulonglong2 w01 = wp[0];
                    ulonglong2 w23 = wp[1];
                    ulonglong2 w45 = wp[2];
                    ulonglong2 w67 = wp[3];
#pragma unroll
                    for (int i = 0; i < RT; i++) {
                        fma2(acc[0][i], qd[i][kx], w01.x);
                        fma2(acc[1][i], qd[i][kx], w01.y);
                        fma2(acc[2][i], qd[i][kx], w23.x);
                        fma2(acc[3][i], qd[i][kx], w23.y);
                        fma2(acc[4][i], qd[i][kx], w45.x);
                        fma2(acc[5][i], qd[i][kx], w45.y);
                        fma2(acc[6][i], qd[i][kx], w67.x);
                        fma2(acc[7][i], qd[i][kx], w67.y);
                    }
                }
            }
        }
    };

    float* buf0 = smdyn;
    float* buf1 = smdyn + BUF;
    stage(0, buf0);
    __syncthreads();
    int nch = Cin / ICT;
    for (int ch = 0; ch < nch; ch++) {
        const float* cb = (ch & 1) ? buf1 : buf0;
        compute(cb);
        if (ch + 1 < nch) {
            stage((ch + 1) * ICT, (ch & 1) ? buf0 : buf1);
            __syncthreads();
        }
    }

#pragma unroll
    for (int j = 0; j < 8; j++) {
#pragma unroll
        for (int i = 0; i < RT; i++) {
            float lo, hi;
            upk(acc[j][i], lo, hi);
            long o0 = ((long)n * Cout + ocb + 2 * j) * (COLS * COLS)
                    + (oy0 + rl0 + i) * COLS + c;
            out[o0] = lo;
            out[o0 + COLS * COLS] = hi;   // next oc channel (COLS x COLS output)
        }
    }
}

// ---------------------------------------------------------------------------
// k4 s2 p1 transposed conv via parity classes, oc-packed fma2.
// blockIdx.z = class (a,b). Sub-grid = input grid (COLS x COLS); block covers
// RB sub-rows. Tap order per acc: (ky asc, kx asc) within the class.
// ---------------------------------------------------------------------------
template <int COLS, int RB, int ICT>
__global__ void __launch_bounds__(256, 2)
convt3_k(const float* __restrict__ in, const float* __restrict__ w,
         const float* __restrict__ bias, float* __restrict__ out,
         int Cin, int Cout, int npx)
{
    constexpr int HL = 32 / COLS;
    constexpr int RT = RB / (2 * HL);
    constexpr int SROWS = RB + 2;
    constexpr int SLOTW = COLS + 2;
    constexpr int SU = ICT * SROWS * SLOTW;
    constexpr int SW = ICT * 4 * 64;
    constexpr int BUF = SU + SW;
    extern __shared__ float smdyn[];

    int n   = blockIdx.y;
    int cls = blockIdx.z;
    int a = cls >> 1, b = cls & 1;
    int pxt = blockIdx.x % npx;
    int oct = blockIdx.x / npx;
    int tid = threadIdx.x;
    int wrp = tid >> 5, lane = tid & 31;
    int og = wrp >> 1, rg = wrp & 1;
    int c  = lane % COLS, h = lane / COLS;
    int sy0 = pxt * RB;
    int ocb = oct * 64 + og * 16;
    int rl0 = rg * (RB / 2) + h * RT;
    int Wout = 2 * COLS;

    u64 acc[8][RT];
#pragma unroll
    for (int j = 0; j < 8; j++) {
        u64 b2 = pk(bias[ocb + 2 * j], bias[ocb + 2 * j + 1]);
#pragma unroll
        for (int i = 0; i < RT; i++) acc[j][i] = b2;
    }

    auto stage = [&](int ic0, float* buf) {
        float* su = buf;
        float* swp = buf + SU;
        const float* ibase = in + ((long)n * Cin + ic0) * (long)(COLS * COLS);
        for (int i = tid; i < SU; i += 256) {
            int s = i % SLOTW;
            int j = (i / SLOTW) % SROWS;
            int icl = i / (SLOTW * SROWS);
            int x = s - 1;
            int iy = sy0 - 1 + j;
            float v = 0.f;
            if ((unsigned)x < (unsigned)COLS && (unsigned)iy < (unsigned)COLS)
                v = ibase[(long)icl * (COLS * COLS) + iy * COLS + x];
            su[i] = v;
        }
        for (int i = tid; i < SW; i += 256) {
            int oc  = i & 63;
            int t   = (i >> 6) & 3;
            int icl = i >> 8;
            int ky = 1 - a + 2 * (t >> 1);
            int kx = 1 - b + 2 * (t & 1);
            swp[i] = w[((long)(ic0 + icl) * Cout + oct * 64 + oc) * 16 + ky * 4 + kx];
        }
    };

    auto compute = [&](const float* buf) {
        const float* su = buf;
        const float* swp = buf + SU;
#pragma unroll 1
        for (int icl = 0; icl < ICT; icl++) {
            u64 qd[RT][4];
#pragma unroll
            for (int i = 0; i < RT; i++) {
                const float* r0 = su + (icl * SROWS + rl0 + i + a + 1) * SLOTW; // iy = s+a
                const float* r1 = su + (icl * SROWS + rl0 + i + a) * SLOTW;     // iy = s+a-1
                float v0 = r0[c + b + 1];   // tap (1-a, 1-b)
                float v1 = r0[c + b];       // tap (1-a, 3-b)
                float v2 = r1[c + b + 1];   // tap (3-a, 1-b)
                float v3 = r1[c + b];       // tap (3-a, 3-b)
                qd[i][0] = pk(v0, v0);
                qd[i][1] = pk(v1, v1);
                qd[i][2] = pk(v2, v2);
                qd[i][3] = pk(v3, v3);
            }
#pragma unroll
            for (int t = 0; t < 4; t++) {
                const ulonglong2* wp = (const ulonglong2*)(swp + (icl * 4 + t) * 64 + og * 16);
                ulonglong2 w01 = wp[0];
                ulonglong2 w23 = wp[1];
                ulonglong2 w45 = wp[2];
                ulonglong2 w67 = wp[3];
#pragma unroll
                for (int i = 0; i < RT; i++) {
                    fma2(acc[0][i], qd[i][t], w01.x);
                    fma2(acc[1][i], qd[i][t], w01.y);
                    fma2(acc[2][i], qd[i][t], w23.x);
                    fma2(acc[3][i], qd[i][t], w23.y);
                    fma2(acc[4][i], qd[i][t], w45.x);
                    fma2(acc[5][i], qd[i][t], w45.y);
                    fma2(acc[6][i], qd[i][t], w67.x);
                    fma2(acc[7][i], qd[i][t], w67.y);
                }
            }
        }
    };

    float* buf0 = smdyn;
    float* buf1 = smdyn + BUF;
    stage(0, buf0);
    __syncthreads();
    int nch = Cin / ICT;
    for (int ch = 0; ch < nch; ch++) {
        const float* cb = (ch & 1) ? buf1 : buf0;
        compute(cb);
        if (ch + 1 < nch) {
            stage((ch + 1) * ICT, (ch & 1) ? buf0 : buf1);
            __syncthreads();
        }
    }

#pragma unroll
    for (int j = 0; j < 8; j++) {
#pragma unroll
        for (int i = 0; i < RT; i++) {
            float lo, hi;
            upk(acc[j][i], lo, hi);
            long o0 = ((long)n * Cout + ocb + 2 * j) * (long)(4 * COLS * COLS)
                    + (long)(2 * (sy0 + rl0 + i) + a) * Wout + 2 * c + b;
            out[o0] = lo;
            out[o0 + (long)4 * COLS * COLS] = hi;   // FIX: next oc channel (Wout x Wout)
        }
    }
}

// ---------------------------------------------------------------------------
// conv1 (3->64 k3 s1 p1) — small layer, round-3 kernel kept.
// ---------------------------------------------------------------------------
template <int K, int S, int P, int ICT>
__global__ void __launch_bounds__(256)
convf_k(const float* __restrict__ in, const float* __restrict__ w,
        const float* __restrict__ bias, float* __restrict__ out,
        int Cin, int Hin, int Win, int Cout, int Hout, int Wout,
        int wsh, int npx)
{
    const int KP = (K == 3) ? 12 : 16;
    __shared__ u64 ws2[ICT * 64 * ((K == 3) ? 12 : 16)];

    int n    = blockIdx.y;
    int pxt  = blockIdx.x % npx;
    int oct  = blockIdx.x / npx;
    int tid  = threadIdx.x;
    int g    = tid >> 5;
    int lane = tid & 31;
    int hw0  = pxt * 128 + lane * 4;
    int oy   = hw0 >> wsh;
    int ox0  = hw0 & (Wout - 1);
    int ocb  = oct * 64 + g * 8;

    const int US = 3 * S + K;
    int xbase = ox0 * S - P;

    u64 acc[8][2];
#pragma unroll
    for (int o = 0; o < 8; o++) {
        float b = bias[ocb + o];
        acc[o][0] = pk(b, b);
        acc[o][1] = pk(b, b);
    }

    long inb = (long)n * Cin * Hin * Win;

    for (int ic0 = 0; ic0 < Cin; ic0 += ICT) {
        __syncthreads();
        for (int i = tid; i < ICT * 64 * 12; i += 256) ws2[i] = 0ull;
        __syncthreads();
        for (int i = tid; i < ICT * 64 * 9; i += 256) {
            int kk = i % 9; int oc = (i / 9) % 64; int ic = i / (9 * 64);
            float v = w[((long)(oct * 64 + oc) * Cin + ic0 + ic) * 9 + kk];
            ws2[(ic * 64 + oc) * 12 + (kk / 3) * 4 + kk % 3] = pk(v, v);
        }
        __syncthreads();

        for (int ic = 0; ic < ICT; ic++) {
            const float* ib = in + inb + (long)(ic0 + ic) * Hin * Win;
#pragma unroll
            for (int ky = 0; ky < K; ky++) {
                int iy = oy * S - P + ky;
                bool yv = (unsigned)iy < (unsigned)Hin;
                const float* rp = ib + iy * Win;
                float u[US];
#pragma unroll
                for (int t = 0; t < US; t++) {
                    int x = xbase + t;
                    u[t] = (yv && (unsigned)x < (unsigned)Win) ? rp[x] : 0.f;
                }
                u64 U0[K], U1[K];
#pragma unroll
                for (int kx = 0; kx < K; kx++) {
                    U0[kx] = pk(u[kx], u[kx + S]);
                    U1[kx] = pk(u[kx + 2 * S], u[kx + 3 * S]);
                }
#pragma unroll
                for (int o = 0; o < 8; o++) {
                    const u64* wb = ws2 + (ic * 64 + g * 8 + o) * KP + ky * 4;
                    ulonglong2 w01 = ((const ulonglong2*)wb)[0];
                    u64 w2 = wb[2];
                    fma2(acc[o][0], U0[0], w01.x); fma2(acc[o][1], U1[0], w01.x);
                    fma2(acc[o][0], U0[1], w01.y); fma2(acc[o][1], U1[1], w01.y);
                    fma2(acc[o][0], U0[2], w2);    fma2(acc[o][1], U1[2], w2);
                }
            }
        }
    }

    long ob = ((long)n * Cout + ocb) * Hout * Wout + hw0;
#pragma unroll
    for (int o = 0; o < 8; o++) {
        float4 v;
        upk(acc[o][0], v.x, v.y);
        upk(acc[o][1], v.z, v.w);
        *(float4*)(out + ob + (long)o * Hout * Wout) = v;
    }
}

// ---------------------------------------------------------------------------
// 1x1 conv / convT as GEMM (unchanged).
// ---------------------------------------------------------------------------
template <int ICT, bool TRANS>
__global__ void __launch_bounds__(256)
gemm1x1_k(const float* __restrict__ in, const float* __restrict__ w,
          const float* __restrict__ bias, float* __restrict__ out,
          int Cin, int HW, int Cout, int npx)
{
    __shared__ u64 ws2[ICT * 64];
    int n = blockIdx.y;
    int pxt = blockIdx.x % npx, oct = blockIdx.x / npx;
    int tid = threadIdx.x;
    int g = tid >> 5, lane = tid & 31;
    int hw0 = pxt * 128 + lane * 4;
    int ocb = oct * 64 + g * 8;

    u64 acc[8][2];
#pragma unroll
    for (int o = 0; o < 8; o++) {
        float b = bias[ocb + o];
        acc[o][0] = pk(b, b);
        acc[o][1] = pk(b, b);
    }

    long inb = (long)n * Cin * HW + hw0;

    for (int ic0 = 0; ic0 < Cin; ic0 += ICT) {
        __syncthreads();
        for (int i = tid; i < ICT * 64; i += 256) {
            int oc = i & 63, ic = i >> 6;
            float v = TRANS ? w[(long)(ic0 + ic) * Cout + oct * 64 + oc]
                            : w[(long)(oct * 64 + oc) * Cin + ic0 + ic];
            ws2[i] = pk(v, v);
        }
        __syncthreads();

        for (int ic = 0; ic < ICT; ic++) {
            float4 v = *(const float4*)(in + inb + (long)(ic0 + ic) * HW);
            u64 U0 = pk(v.x, v.y), U1 = pk(v.z, v.w);
            const ulonglong2* wp = (const ulonglong2*)(ws2 + ic * 64 + g * 8);
#pragma unroll
            for (int k = 0; k < 4; k++) {
                ulonglong2 ww = wp[k];
                fma2(acc[2 * k][0], U0, ww.x);     fma2(acc[2 * k][1], U1, ww.x);
                fma2(acc[2 * k + 1][0], U0, ww.y); fma2(acc[2 * k + 1][1], U1, ww.y);
            }
        }
    }

    long ob = ((long)n * Cout + ocb) * HW + hw0;
#pragma unroll
    for (int o = 0; o < 8; o++) {
        float4 v;
        upk(acc[o][0], v.x, v.y);
        upk(acc[o][1], v.z, v.w);
        *(float4*)(out + ob + (long)o * HW) = v;
    }
}

// ---------------------------------------------------------------------------
// Final conv 64 -> 3, k3 s1 p1 (unchanged).
// ---------------------------------------------------------------------------
__global__ void __launch_bounds__(256)
convlast_k(const float* __restrict__ in, const float* __restrict__ w,
           const float* __restrict__ bias, float* __restrict__ out)
{
    __shared__ u64 ws2[64 * 3 * 12];
    int n = blockIdx.y;
    int pxt = blockIdx.x;
    int tid = threadIdx.x;
    int hw0 = pxt * 1024 + tid * 4;
    int oy = hw0 >> 6, ox0 = hw0 & 63;

    for (int i = tid; i < 64 * 3 * 12; i += 256) ws2[i] = 0ull;
    __syncthreads();
    for (int i = tid; i < 64 * 3 * 9; i += 256) {
        int kk = i % 9; int t = i / 9; int oc = t % 3; int ic = t / 3;
        float v = w[((long)oc * 64 + ic) * 9 + kk];
        ws2[((ic * 3 + oc) * 3 + kk / 3) * 4 + kk % 3] = pk(v, v);
    }
    __syncthreads();

    u64 acc[3][2];
#pragma unroll
    for (int o = 0; o < 3; o++) {
        float b = bias[o];
        acc[o][0] = pk(b, b);
        acc[o][1] = pk(b, b);
    }

    const float* ib = in + (long)n * 64 * 4096;
    for (int ic = 0; ic < 64; ic++) {
        const float* ibc = ib + (long)ic * 4096;
#pragma unroll
        for (int ky = 0; ky < 3; ky++) {
            int iy = oy - 1 + ky;
            bool yv = (unsigned)iy < 64u;
            const float* rp = ibc + iy * 64;
            float u[6];
#pragma unroll
            for (int t = 0; t < 6; t++) {
                int x = ox0 - 1 + t;
                u[t] = (yv && (unsigned)x < 64u) ? rp[x] : 0.f;
            }
            u64 U0[3], U1[3];
#pragma unroll
            for (int kx = 0; kx < 3; kx++) {
                U0[kx] = pk(u[kx], u[kx + 1]);
                U1[kx] = pk(u[kx + 2], u[kx + 3]);
            }
#pragma unroll
            for (int o = 0; o < 3; o++) {
                const u64* wb = ws2 + ((ic * 3 + o) * 3 + ky) * 4;
                ulonglong2 w01 = ((const ulonglong2*)wb)[0];
                u64 w2 = wb[2];
                fma2(acc[o][0], U0[0], w01.x); fma2(acc[o][1], U1[0], w01.x);
                fma2(acc[o][0], U0[1], w01.y); fma2(acc[o][1], U1[1], w01.y);
                fma2(acc[o][0], U0[2], w2);    fma2(acc[o][1], U1[2], w2);
            }
        }
    }

#pragma unroll
    for (int o = 0; o < 3; o++) {
        float4 v;
        upk(acc[o][0], v.x, v.y);
        upk(acc[o][1], v.z, v.w);
        *(float4*)(out + ((long)n * 3 + o) * 4096 + hw0) = v;
    }
}

// ---------------------------------------------------------------------------
// BatchNorm stats (unchanged — bit-identical scale/shift).
// ---------------------------------------------------------------------------
__global__ void bn_stats_k(const float* __restrict__ x, const float* __restrict__ g,
                           const float* __restrict__ be, float* __restrict__ scale,
                           float* __restrict__ shift, int C, int N, int HW)
{
    int c = blockIdx.x;
    int tid = threadIdx.x;
    float s = 0.f, ss = 0.f;
    for (int n = 0; n < N; n++) {
        const float* p = x + ((long)(n * C + c)) * HW;
        for (int r = tid; r < HW; r += blockDim.x) {
            float v = p[r];
            s += v; ss += v * v;
        }
    }
    __shared__ float sh1[1024];
    __shared__ float sh2[1024];
    sh1[tid] = s; sh2[tid] = ss;
    __syncthreads();
    for (int ofs = blockDim.x >> 1; ofs > 0; ofs >>= 1) {
        if (tid < ofs) { sh1[tid] += sh1[tid + ofs]; sh2[tid] += sh2[tid + ofs]; }
        __syncthreads();
    }
    if (tid == 0) {
        float cnt = (float)N * (float)HW;
        float m = sh1[0] / cnt;
        float var = sh2[0] / cnt - m * m;
        float sc = g[c] * rsqrtf(var + 1e-5f);
        scale[c] = sc;
        shift[c] = be[c] - m * sc;
    }
}

__global__ void bn_apply4_k(float4* __restrict__ x, const float* __restrict__ scale,
                            const float* __restrict__ shift, int C, int hwsh, int total4)
{
    int i = blockIdx.x * blockDim.x + threadIdx.x;
    if (i >= total4) return;
    int c = (i >> hwsh) % C;
    float s = scale[c], t = shift[c];
    float4 v = x[i];
    v.x = fmaxf(fmaf(v.x, s, t), 0.f);
    v.y = fmaxf(fmaf(v.y, s, t), 0.f);
    v.z = fmaxf(fmaf(v.z, s, t), 0.f);
    v.w = fmaxf(fmaf(v.w, s, t), 0.f);
    x[i] = v;
}

__global__ void cc_k(const float* __restrict__ cb, float* __restrict__ cc)
{
    int j = blockIdx.x * blockDim.x + threadIdx.x;
    if (j >= 256) return;
    double s = 0.0;
    const float* row = cb + (long)j * 256;
    for (int d = 0; d < 256; d++) {
        double v = (double)row[d];
        s += v * v;
    }
    cc[j] = (float)s;
}

// ---------------------------------------------------------------------------
// VQ with reference-exact fp32 distance emulation (unchanged).
// ---------------------------------------------------------------------------
__global__ void vq_exact_k(const float* __restrict__ h, const float* __restrict__ cb,
                           const float* __restrict__ cc, float* __restrict__ hq,
                           float* __restrict__ lossp)
{
    const int POS = 64;
    int b = blockIdx.x >> 2;
    int hw0 = (blockIdx.x & 3) * POS;
    int p = threadIdx.x;

    __shared__ float zs[256 * POS];
    __shared__ float cbs[8 * 256];
    __shared__ float ccs[8];

    const float* hb = h + (long)b * 256 * 256 + hw0;
    for (int d = 0; d < 256; d++)
        zs[d * POS + p] = hb[d * 256 + p];
    __syncthreads();

    float zz = 0.f;
    for (int d = 0; d < 256; d++) {
        float z = zs[d * POS + p];
        zz = fmaf(z, z, zz);
    }

    float best = CUDART_INF_F;
    int bj = 0;

    for (int jc = 0; jc < 256; jc += 8) {
        __syncthreads();
        for (int t = p; t < 8 * 256; t += POS)
            cbs[t] = cb[jc * 256 + t];
        if (p < 8) ccs[p] = cc[jc + p];
        __syncthreads();

        float acc[8];
#pragma unroll
        for (int q = 0; q < 8; q++) acc[q] = 0.f;

        for (int dc = 0; dc < 256; dc += 32) {
            float zreg[32];
#pragma unroll
            for (int d = 0; d < 32; d++)
                zreg[d] = zs[(dc + d) * POS + p];
#pragma unroll
            for (int q = 0; q < 8; q++) {
#pragma unroll
                for (int d = 0; d < 32; d++)
                    acc[q] = fmaf(zreg[d], cbs[q * 256 + dc + d], acc[q]);
            }
        }

#pragma unroll
        for (int q = 0; q < 8; q++) {
            float d2 = (zz + ccs[q]) - 2.0f * acc[q];
            if (d2 < best) { best = d2; bj = jc + q; }
        }
    }

    const float* crow = cb + (long)bj * 256;
    float* hqb = hq + (long)b * 256 * 256 + hw0;
    float l = 0.f;
    for (int d = 0; d < 256; d++) {
        float c = crow[d];
        hqb[d * 256 + p] = c;
        float diff = zs[d * POS + p] - c;
        l = fmaf(diff, diff, l);
    }
    lossp[b * 256 + hw0 + p] = l;
}

__global__ void loss_reduce_k(const float* __restrict__ lossp, float* __restrict__ out2)
{
    int tid = threadIdx.x;
    double s = 0.0;
    for (int i = tid; i < 32768; i += 1024) s += (double)lossp[i];
    __shared__ double sh[1024];
    sh[tid] = s;
    __syncthreads();
    for (int ofs = 512; ofs > 0; ofs >>= 1) {
        if (tid < ofs) sh[tid] += sh[tid + ofs];
        __syncthreads();
    }
    if (tid == 0) {
        float m = (float)(sh[0] / 32768.0);
        out2[0] = m;
        out2[1] = m;
    }
}

// ---------------------------------------------------------------------------
static inline int gridFor(int total, int block) { return (total + block - 1) / block; }

extern "C" void kernel_launch(void* const* d_in, const int* in_sizes, int n_in,
                              void* d_out, int out_size)
{
    const float* x        = (const float*)d_in[0];
    const float* codebook = (const float*)d_in[1];
    const float* e_w1 = (const float*)d_in[2];  const float* e_b1 = (const float*)d_in[3];
    const float* e_g1 = (const float*)d_in[4];  const float* e_be1 = (const float*)d_in[5];
    const float* e_w2 = (const float*)d_in[6];  const float* e_b2 = (const float*)d_in[7];
    const float* e_g2 = (const float*)d_in[8];  const float* e_be2 = (const float*)d_in[9];
    const float* e_w3 = (const float*)d_in[10]; const float* e_b3 = (const float*)d_in[11];
    const float* e_g3 = (const float*)d_in[12]; const float* e_be3 = (const float*)d_in[13];
    const float* e_w4 = (const float*)d_in[14]; const float* e_b4 = (const float*)d_in[15];
    const float* d_w1 = (const float*)d_in[16]; const float* d_b1 = (const float*)d_in[17];
    const float* d_g1 = (const float*)d_in[18]; const float* d_be1 = (const float*)d_in[19];
    const float* d_w2 = (const float*)d_in[20]; const float* d_b2 = (const float*)d_in[21];
    const float* d_g2 = (const float*)d_in[22]; const float* d_be2 = (const float*)d_in[23];
    const float* d_w3 = (const float*)d_in[24]; const float* d_b3 = (const float*)d_in[25];
    const float* d_g3 = (const float*)d_in[26]; const float* d_be3 = (const float*)d_in[27];
    const float* d_w4 = (const float*)d_in[28]; const float* d_b4 = (const float*)d_in[29];

    float* out = (float*)d_out;

    float *a1, *a2, *a3, *h4, *hq, *b1, *b2, *b3, *scale, *shift, *lossp, *cc;
    cudaGetSymbolAddress((void**)&a1, g_a1);
    cudaGetSymbolAddress((void**)&a2, g_a2);
    cudaGetSymbolAddress((void**)&a3, g_a3);
    cudaGetSymbolAddress((void**)&h4, g_h4);
    cudaGetSymbolAddress((void**)&hq, g_hq);
    cudaGetSymbolAddress((void**)&b1, g_d1);
    cudaGetSymbolAddress((void**)&b2, g_d2);
    cudaGetSymbolAddress((void**)&b3, g_d3);
    cudaGetSymbolAddress((void**)&scale, g_scale);
    cudaGetSymbolAddress((void**)&shift, g_shift);
    cudaGetSymbolAddress((void**)&lossp, g_lossp);
    cudaGetSymbolAddress((void**)&cc, g_cc);

    const int N = 128;

    // dynamic smem sizes (2 buffers each)
    const int SM_C2 = 2 * (4 * 18 * 66 + 4 * 16 * 64) * 4;   // 70784 B
    const int SM_C3 = 2 * (4 * 18 * 34 + 4 * 16 * 64) * 4;   // 52352 B
    const int SM_D2 = 2 * (8 * 18 * 18 + 8 * 4 * 64) * 4;    // 37120 B
    const int SM_D3 = 2 * (8 * 10 * 34 + 8 * 4 * 64) * 4;    // 38144 B
    cudaFuncSetAttribute(convf3_k<32, 8, 4>, cudaFuncAttributeMaxDynamicSharedMemorySize, SM_C2);
    cudaFuncSetAttribute(convf3_k<16, 8, 4>, cudaFuncAttributeMaxDynamicSharedMemorySize, SM_C3);
    cudaFuncSetAttribute(convt3_k<16, 16, 8>, cudaFuncAttributeMaxDynamicSharedMemorySize, SM_D2);
    cudaFuncSetAttribute(convt3_k<32, 8, 8>, cudaFuncAttributeMaxDynamicSharedMemorySize, SM_D3);

    // ---- encoder ----
    // conv1: 3 -> 64, k3 s1 p1
    convf_k<3, 1, 1, 3><<<dim3(32, N), 256>>>(x, e_w1, e_b1, a1,
                                              3, 64, 64, 64, 64, 64, 6, 32);
    bn_stats_k<<<64, 1024>>>(a1, e_g1, e_be1, scale, shift, 64, N, 4096);
    bn_apply4_k<<<gridFor(N * 64 * 1024, 256), 256>>>((float4*)a1, scale, shift, 64, 10,
                                                      N * 64 * 1024);

    // conv2: 64 -> 128, k4 s2 p1, 64->32 (COLS=32, RB=8: npx=4, oct=2)
    convf3_k<32, 8, 4><<<dim3(4 * 2, N), 256, SM_C2>>>(a1, e_w2, e_b2, a2, 64, 128, 4);
    bn_stats_k<<<128, 1024>>>(a2, e_g2, e_be2, scale, shift, 128, N, 1024);
    bn_apply4_k<<<gridFor(N * 128 * 256, 256), 256>>>((float4*)a2, scale, shift, 128, 8,
                                                      N * 128 * 256);

    // conv3: 128 -> 192, k4 s2 p1, 32->16 (COLS=16, RB=8: npx=2, oct=3)
    convf3_k<16, 8, 4><<<dim3(2 * 3, N), 256, SM_C3>>>(a2, e_w3, e_b3, a3, 128, 192, 2);
    bn_stats_k<<<192, 1024>>>(a3, e_g3, e_be3, scale, shift, 192, N, 256);
    bn_apply4_k<<<gridFor(N * 192 * 64, 256), 256>>>((float4*)a3, scale, shift, 192, 6,
                                                     N * 192 * 64);

    // conv4: 192 -> 256, 1x1
    gemm1x1_k<32, false><<<dim3(2 * 4, N), 256>>>(a3, e_w4, e_b4, h4, 192, 256, 256, 2);

    // ---- vector quantization ----
    cc_k<<<1, 256>>>(codebook, cc);
    vq_exact_k<<<512, 64>>>(h4, codebook, cc, hq, lossp);
    loss_reduce_k<<<1, 1024>>>(lossp, out + (out_size - 2));

    // ---- decoder ----
    // d1: convT 1x1, 256 -> 192
    gemm1x1_k<32, true><<<dim3(2 * 3, N), 256>>>(hq, d_w1, d_b1, b1, 256, 256, 192, 2);
    bn_stats_k<<<192, 1024>>>(b1, d_g1, d_be1, scale, shift, 192, N, 256);
    bn_apply4_k<<<gridFor(N * 192 * 64, 256), 256>>>((float4*)b1, scale, shift, 192, 6,
                                                     N * 192 * 64);

    // d2: convT 192 -> 128, 16->32 (COLS=16, RB=16: npx=1, oct=2, 4 classes)
    convt3_k<16, 16, 8><<<dim3(1 * 2, N, 4), 256, SM_D2>>>(b1, d_w2, d_b2, b2, 192, 128, 1);
    bn_stats_k<<<128, 1024>>>(b2, d_g2, d_be2, scale, shift, 128, N, 1024);
    bn_apply4_k<<<gridFor(N * 128 * 256, 256), 256>>>((float4*)b2, scale, shift, 128, 8,
                                                      N * 128 * 256);

    // d3: convT 128 -> 64, 32->64 (COLS=32, RB=8: npx=4, oct=1, 4 classes)
    convt3_k<32, 8, 8><<<dim3(4 * 1, N, 4), 256, SM_D3>>>(b2, d_w3, d_b3, b3, 128, 64, 4);
    bn_stats_k<<<64, 1024>>>(b3, d_g3, d_be3, scale, shift, 64, N, 4096);
    bn_apply4_k<<<gridFor(N * 64 * 1024, 256), 256>>>((float4*)b3, scale, shift, 64, 10,
                                                      N * 64 * 1024);

    // d4: conv 64 -> 3, k3 s1 p1 -> final output
    convlast_k<<<dim3(4, N), 256>>>(b3, d_w4, d_b4, out);
}

// round 7
// speedup vs baseline: 8.8320x; 1.1739x over previous
#include <cuda_runtime.h>
#include <math_constants.h>

typedef unsigned long long u64;

__device__ __forceinline__ u64 pk(float lo, float hi) {
    u64 r;
    asm("mov.b64 %0, {%1, %2};" : "=l"(r) : "f"(lo), "f"(hi));
    return r;
}
__device__ __forceinline__ void upk(u64 v, float& lo, float& hi) {
    asm("mov.b64 {%0, %1}, %2;" : "=f"(lo), "=f"(hi) : "l"(v));
}
__device__ __forceinline__ void fma2(u64& d, u64 a, u64 b) {
    asm("fma.rn.f32x2 %0, %1, %2, %0;" : "+l"(d) : "l"(a), "l"(b));
}
__device__ __forceinline__ unsigned s2u(const void* p) {
    return (unsigned)__cvta_generic_to_shared(p);
}
__device__ __forceinline__ void cpa4(unsigned saddr, const float* g, bool v) {
    int sz = v ? 4 : 0;
    asm volatile("cp.async.ca.shared.global [%0], [%1], 4, %2;"
                 :: "r"(saddr), "l"(g), "r"(sz) : "memory");
}
__device__ __forceinline__ void cpa16(unsigned saddr, const float* g) {
    asm volatile("cp.async.cg.shared.global [%0], [%1], 16;"
                 :: "r"(saddr), "l"(g) : "memory");
}
#define CP_COMMIT() asm volatile("cp.async.commit_group;" ::: "memory")
#define CP_WAIT0()  asm volatile("cp.async.wait_group 0;" ::: "memory")

// Scratch buffers
__device__ float g_a1[128 * 64 * 64 * 64];
__device__ float g_a2[128 * 128 * 32 * 32];
__device__ float g_a3[128 * 192 * 16 * 16];
__device__ float g_h4[128 * 256 * 16 * 16];
__device__ float g_hq[128 * 256 * 16 * 16];
__device__ float g_d1[128 * 192 * 16 * 16];
__device__ float g_d2[128 * 128 * 32 * 32];
__device__ float g_d3[128 * 64 * 64 * 64];
__device__ float g_scale[256];
__device__ float g_shift[256];
__device__ float g_lossp[32768];
__device__ float g_cc[256];
// transposed weights (tap-major: [(ic*16 + tap)*Cout + oc])
__device__ float g_wt2[64 * 16 * 128];
__device__ float g_wt3[128 * 16 * 192];
__device__ float g_wtd2[192 * 16 * 128];
__device__ float g_wtd3[128 * 16 * 64];

// weight transpose: forward conv w[oc][ic][16] -> wt[(ic*16+t)*Cout+oc]
__global__ void wtr_fwd_k(const float* __restrict__ w, float* __restrict__ wt,
                          int Cin, int Cout)
{
    int i = blockIdx.x * 256 + threadIdx.x;
    int total = Cin * Cout * 16;
    if (i >= total) return;
    int oc = i % Cout; int r = i / Cout;
    int t = r & 15; int ic = r >> 4;
    wt[i] = w[((long)oc * Cin + ic) * 16 + t];
}
// transposed conv w[ic][oc][16] -> wt[(ic*16+t)*Cout+oc]
__global__ void wtr_tr_k(const float* __restrict__ w, float* __restrict__ wt,
                         int Cin, int Cout)
{
    int i = blockIdx.x * 256 + threadIdx.x;
    int total = Cin * Cout * 16;
    if (i >= total) return;
    int oc = i % Cout; int r = i / Cout;
    int t = r & 15; int ic = r >> 4;
    wt[i] = w[((long)ic * Cout + oc) * 16 + t];
}

// ---------------------------------------------------------------------------
// k4 s2 p1 forward conv, oc-packed fma2, cp.async double-buffered staging.
// Chain per output: bias; (ic asc, ky asc, kx asc); zero-filled borders.
// ---------------------------------------------------------------------------
template <int COLS, int RB, int ICT>
__global__ void __launch_bounds__(256, 2)
convf3_k(const float* __restrict__ in, const float* __restrict__ wt,
         const float* __restrict__ bias, float* __restrict__ out,
         int Cin, int Cout, int npx)
{
    constexpr int HL = 32 / COLS;
    constexpr int RT = RB / (2 * HL);
    constexpr int SROWS = 2 * RB + 2;
    constexpr int SLOTW = 2 * COLS + 2;
    constexpr int SU = ICT * SROWS * SLOTW;
    constexpr int SW = ICT * 16 * 64;
    constexpr int BUF = SU + SW;
    extern __shared__ float smdyn[];

    const int Win = 2 * COLS, Hin = 2 * COLS;

    int n   = blockIdx.y;
    int pxt = blockIdx.x % npx;
    int oct = blockIdx.x / npx;
    int tid = threadIdx.x;
    int wrp = tid >> 5, lane = tid & 31;
    int og = wrp >> 1, rg = wrp & 1;
    int c  = lane % COLS, h = lane / COLS;
    int oy0 = pxt * RB;
    int ocb = oct * 64 + og * 16;
    int rl0 = rg * (RB / 2) + h * RT;

    u64 acc[8][RT];
#pragma unroll
    for (int j = 0; j < 8; j++) {
        u64 b2 = pk(bias[ocb + 2 * j], bias[ocb + 2 * j + 1]);
#pragma unroll
        for (int i = 0; i < RT; i++) acc[j][i] = b2;
    }

    auto stage = [&](int ic0, float* buf) {
        unsigned su_s = s2u(buf);
        unsigned sw_s = s2u(buf + SU);
        const float* ibase = in + ((long)n * Cin + ic0) * (long)(Hin * Win);
        for (int i = tid; i < SU; i += 256) {
            int s = i % SLOTW;
            int j = (i / SLOTW) % SROWS;
            int icl = i / (SLOTW * SROWS);
            int x = s - 1;
            int iy = 2 * oy0 - 1 + j;
            bool vld = (unsigned)x < (unsigned)Win && (unsigned)iy < (unsigned)Hin;
            const float* gp = vld ? ibase + (long)icl * (Hin * Win) + iy * Win + x
                                  : ibase;
            cpa4(su_s + i * 4, gp, vld);
        }
        // weights: wt[(ic*16+t)*Cout + oc], contiguous oc -> 16B copies
        for (int i4 = tid; i4 < SW / 4; i4 += 256) {
            int i = i4 * 4;
            int oc = i & 63;
            int row = i >> 6;          // icl*16 + tap
            const float* gp = wt + ((long)(ic0 * 16 + row)) * Cout + oct * 64 + oc;
            cpa16(sw_s + i * 4, gp);
        }
    };

    auto compute = [&](const float* buf) {
        const float* su = buf;
        const float* swp = buf + SU;
#pragma unroll 1
        for (int icl = 0; icl < ICT; icl++) {
#pragma unroll
            for (int ky = 0; ky < 4; ky++) {
                u64 qd[RT][4];
#pragma unroll
                for (int i = 0; i < RT; i++) {
                    const float* row = su + (icl * SROWS + 2 * (rl0 + i) + ky) * SLOTW + 2 * c;
                    float2 f01 = *(const float2*)(row);
                    float2 f23 = *(const float2*)(row + 2);
                    qd[i][0] = pk(f01.x, f01.x);
                    qd[i][1] = pk(f01.y, f01.y);
                    qd[i][2] = pk(f23.x, f23.x);
                    qd[i][3] = pk(f23.y, f23.y);
                }
#pragma unroll
                for (int kx = 0; kx < 4; kx++) {
                    const ulonglong2* wp =
                        (const ulonglong2*)(swp + (icl * 16 + ky * 4 + kx) * 64 + og * 16);
                    ulonglong2 w01 = wp[0];
                    ulonglong2 w23 = wp[1];
                    ulonglong2 w45 = wp[2];
                    ulonglong2 w67 = wp[3];
#pragma unroll
                    for (int i = 0; i < RT; i++) {
                        fma2(acc[0][i], qd[i][kx], w01.x);
                        fma2(acc[1][i], qd[i][kx], w01.y);
                        fma2(acc[2][i], qd[i][kx], w23.x);
                        fma2(acc[3][i], qd[i][kx], w23.y);
                        fma2(acc[4][i], qd[i][kx], w45.x);
                        fma2(acc[5][i], qd[i][kx], w45.y);
                        fma2(acc[6][i], qd[i][kx], w67.x);
                        fma2(acc[7][i], qd[i][kx], w67.y);
                    }
                }
            }
        }
    };

    float* buf0 = smdyn;
    float* buf1 = smdyn + BUF;
    stage(0, buf0);
    CP_COMMIT();
    CP_WAIT0();
    __syncthreads();
    int nch = Cin / ICT;
    for (int ch = 0; ch < nch; ch++) {
        float* cbuf = (ch & 1) ? buf1 : buf0;
        float* nbuf = (ch & 1) ? buf0 : buf1;
        if (ch + 1 < nch) { stage((ch + 1) * ICT, nbuf); CP_COMMIT(); }
        compute(cbuf);
        if (ch + 1 < nch) { CP_WAIT0(); __syncthreads(); }
    }

#pragma unroll
    for (int j = 0; j < 8; j++) {
#pragma unroll
        for (int i = 0; i < RT; i++) {
            float lo, hi;
            upk(acc[j][i], lo, hi);
            long o0 = ((long)n * Cout + ocb + 2 * j) * (COLS * COLS)
                    + (oy0 + rl0 + i) * COLS + c;
            out[o0] = lo;
            out[o0 + COLS * COLS] = hi;
        }
    }
}

// ---------------------------------------------------------------------------
// k4 s2 p1 transposed conv via parity classes, oc-packed fma2, cp.async.
// ---------------------------------------------------------------------------
template <int COLS, int RB, int ICT>
__global__ void __launch_bounds__(256, 2)
convt3_k(const float* __restrict__ in, const float* __restrict__ wt,
         const float* __restrict__ bias, float* __restrict__ out,
         int Cin, int Cout, int npx)
{
    constexpr int HL = 32 / COLS;
    constexpr int RT = RB / (2 * HL);
    constexpr int SROWS = RB + 2;
    constexpr int SLOTW = COLS + 2;
    constexpr int SU = ICT * SROWS * SLOTW;
    constexpr int SW = ICT * 4 * 64;
    constexpr int BUF = SU + SW;
    extern __shared__ float smdyn[];

    int n   = blockIdx.y;
    int cls = blockIdx.z;
    int a = cls >> 1, b = cls & 1;
    int pxt = blockIdx.x % npx;
    int oct = blockIdx.x / npx;
    int tid = threadIdx.x;
    int wrp = tid >> 5, lane = tid & 31;
    int og = wrp >> 1, rg = wrp & 1;
    int c  = lane % COLS, h = lane / COLS;
    int sy0 = pxt * RB;
    int ocb = oct * 64 + og * 16;
    int rl0 = rg * (RB / 2) + h * RT;
    int Wout = 2 * COLS;

    u64 acc[8][RT];
#pragma unroll
    for (int j = 0; j < 8; j++) {
        u64 b2 = pk(bias[ocb + 2 * j], bias[ocb + 2 * j + 1]);
#pragma unroll
        for (int i = 0; i < RT; i++) acc[j][i] = b2;
    }

    auto stage = [&](int ic0, float* buf) {
        unsigned su_s = s2u(buf);
        unsigned sw_s = s2u(buf + SU);
        const float* ibase = in + ((long)n * Cin + ic0) * (long)(COLS * COLS);
        for (int i = tid; i < SU; i += 256) {
            int s = i % SLOTW;
            int j = (i / SLOTW) % SROWS;
            int icl = i / (SLOTW * SROWS);
            int x = s - 1;
            int iy = sy0 - 1 + j;
            bool vld = (unsigned)x < (unsigned)COLS && (unsigned)iy < (unsigned)COLS;
            const float* gp = vld ? ibase + (long)icl * (COLS * COLS) + iy * COLS + x
                                  : ibase;
            cpa4(su_s + i * 4, gp, vld);
        }
        for (int i4 = tid; i4 < SW / 4; i4 += 256) {
            int i = i4 * 4;
            int oc = i & 63;
            int t  = (i >> 6) & 3;
            int icl = i >> 8;
            int kt = (1 - a + 2 * (t >> 1)) * 4 + (1 - b + 2 * (t & 1));
            const float* gp = wt + ((long)((ic0 + icl) * 16 + kt)) * Cout + oct * 64 + oc;
            cpa16(sw_s + i * 4, gp);
        }
    };

    auto compute = [&](const float* buf) {
        const float* su = buf;
        const float* swp = buf + SU;
#pragma unroll 1
        for (int icl = 0; icl < ICT; icl++) {
            u64 qd[RT][4];
#pragma unroll
            for (int i = 0; i < RT; i++) {
                const float* r0 = su + (icl * SROWS + rl0 + i + a + 1) * SLOTW; // iy = s+a
                const float* r1 = su + (icl * SROWS + rl0 + i + a) * SLOTW;     // iy = s+a-1
                float v0 = r0[c + b + 1];
                float v1 = r0[c + b];
                float v2 = r1[c + b + 1];
                float v3 = r1[c + b];
                qd[i][0] = pk(v0, v0);
                qd[i][1] = pk(v1, v1);
                qd[i][2] = pk(v2, v2);
                qd[i][3] = pk(v3, v3);
            }
#pragma unroll
            for (int t = 0; t < 4; t++) {
                const ulonglong2* wp = (const ulonglong2*)(swp + (icl * 4 + t) * 64 + og * 16);
                ulonglong2 w01 = wp[0];
                ulonglong2 w23 = wp[1];
                ulonglong2 w45 = wp[2];
                ulonglong2 w67 = wp[3];
#pragma unroll
                for (int i = 0; i < RT; i++) {
                    fma2(acc[0][i], qd[i][t], w01.x);
                    fma2(acc[1][i], qd[i][t], w01.y);
                    fma2(acc[2][i], qd[i][t], w23.x);
                    fma2(acc[3][i], qd[i][t], w23.y);
                    fma2(acc[4][i], qd[i][t], w45.x);
                    fma2(acc[5][i], qd[i][t], w45.y);
                    fma2(acc[6][i], qd[i][t], w67.x);
                    fma2(acc[7][i], qd[i][t], w67.y);
                }
            }
        }
    };

    float* buf0 = smdyn;
    float* buf1 = smdyn + BUF;
    stage(0, buf0);
    CP_COMMIT();
    CP_WAIT0();
    __syncthreads();
    int nch = Cin / ICT;
    for (int ch = 0; ch < nch; ch++) {
        float* cbuf = (ch & 1) ? buf1 : buf0;
        float* nbuf = (ch & 1) ? buf0 : buf1;
        if (ch + 1 < nch) { stage((ch + 1) * ICT, nbuf); CP_COMMIT(); }
        compute(cbuf);
        if (ch + 1 < nch) { CP_WAIT0(); __syncthreads(); }
    }

#pragma unroll
    for (int j = 0; j < 8; j++) {
#pragma unroll
        for (int i = 0; i < RT; i++) {
            float lo, hi;
            upk(acc[j][i], lo, hi);
            long o0 = ((long)n * Cout + ocb + 2 * j) * (long)(4 * COLS * COLS)
                    + (long)(2 * (sy0 + rl0 + i) + a) * Wout + 2 * c + b;
            out[o0] = lo;
            out[o0 + (long)4 * COLS * COLS] = hi;
        }
    }
}

// ---------------------------------------------------------------------------
// conv1 (3->64 k3 s1 p1) — small layer (unchanged).
// ---------------------------------------------------------------------------
template <int K, int S, int P, int ICT>
__global__ void __launch_bounds__(256)
convf_k(const float* __restrict__ in, const float* __restrict__ w,
        const float* __restrict__ bias, float* __restrict__ out,
        int Cin, int Hin, int Win, int Cout, int Hout, int Wout,
        int wsh, int npx)
{
    const int KP = (K == 3) ? 12 : 16;
    __shared__ u64 ws2[ICT * 64 * ((K == 3) ? 12 : 16)];

    int n    = blockIdx.y;
    int pxt  = blockIdx.x % npx;
    int oct  = blockIdx.x / npx;
    int tid  = threadIdx.x;
    int g    = tid >> 5;
    int lane = tid & 31;
    int hw0  = pxt * 128 + lane * 4;
    int oy   = hw0 >> wsh;
    int ox0  = hw0 & (Wout - 1);
    int ocb  = oct * 64 + g * 8;

    const int US = 3 * S + K;
    int xbase = ox0 * S - P;

    u64 acc[8][2];
#pragma unroll
    for (int o = 0; o < 8; o++) {
        float b = bias[ocb + o];
        acc[o][0] = pk(b, b);
        acc[o][1] = pk(b, b);
    }

    long inb = (long)n * Cin * Hin * Win;

    for (int ic0 = 0; ic0 < Cin; ic0 += ICT) {
        __syncthreads();
        for (int i = tid; i < ICT * 64 * 12; i += 256) ws2[i] = 0ull;
        __syncthreads();
        for (int i = tid; i < ICT * 64 * 9; i += 256) {
            int kk = i % 9; int oc = (i / 9) % 64; int ic = i / (9 * 64);
            float v = w[((long)(oct * 64 + oc) * Cin + ic0 + ic) * 9 + kk];
            ws2[(ic * 64 + oc) * 12 + (kk / 3) * 4 + kk % 3] = pk(v, v);
        }
        __syncthreads();

        for (int ic = 0; ic < ICT; ic++) {
            const float* ib = in + inb + (long)(ic0 + ic) * Hin * Win;
#pragma unroll
            for (int ky = 0; ky < K; ky++) {
                int iy = oy * S - P + ky;
                bool yv = (unsigned)iy < (unsigned)Hin;
                const float* rp = ib + iy * Win;
                float u[US];
#pragma unroll
                for (int t = 0; t < US; t++) {
                    int x = xbase + t;
                    u[t] = (yv && (unsigned)x < (unsigned)Win) ? rp[x] : 0.f;
                }
                u64 U0[K], U1[K];
#pragma unroll
                for (int kx = 0; kx < K; kx++) {
                    U0[kx] = pk(u[kx], u[kx + S]);
                    U1[kx] = pk(u[kx + 2 * S], u[kx + 3 * S]);
                }
#pragma unroll
                for (int o = 0; o < 8; o++) {
                    const u64* wb = ws2 + (ic * 64 + g * 8 + o) * KP + ky * 4;
                    ulonglong2 w01 = ((const ulonglong2*)wb)[0];
                    u64 w2 = wb[2];
                    fma2(acc[o][0], U0[0], w01.x); fma2(acc[o][1], U1[0], w01.x);
                    fma2(acc[o][0], U0[1], w01.y); fma2(acc[o][1], U1[1], w01.y);
                    fma2(acc[o][0], U0[2], w2);    fma2(acc[o][1], U1[2], w2);
                }
            }
        }
    }

    long ob = ((long)n * Cout + ocb) * Hout * Wout + hw0;
#pragma unroll
    for (int o = 0; o < 8; o++) {
        float4 v;
        upk(acc[o][0], v.x, v.y);
        upk(acc[o][1], v.z, v.w);
        *(float4*)(out + ob + (long)o * Hout * Wout) = v;
    }
}

// ---------------------------------------------------------------------------
// 1x1 conv / convT as GEMM (unchanged).
// ---------------------------------------------------------------------------
template <int ICT, bool TRANS>
__global__ void __launch_bounds__(256)
gemm1x1_k(const float* __restrict__ in, const float* __restrict__ w,
          const float* __restrict__ bias, float* __restrict__ out,
          int Cin, int HW, int Cout, int npx)
{
    __shared__ u64 ws2[ICT * 64];
    int n = blockIdx.y;
    int pxt = blockIdx.x % npx, oct = blockIdx.x / npx;
    int tid = threadIdx.x;
    int g = tid >> 5, lane = tid & 31;
    int hw0 = pxt * 128 + lane * 4;
    int ocb = oct * 64 + g * 8;

    u64 acc[8][2];
#pragma unroll
    for (int o = 0; o < 8; o++) {
        float b = bias[ocb + o];
        acc[o][0] = pk(b, b);
        acc[o][1] = pk(b, b);
    }

    long inb = (long)n * Cin * HW + hw0;

    for (int ic0 = 0; ic0 < Cin; ic0 += ICT) {
        __syncthreads();
        for (int i = tid; i < ICT * 64; i += 256) {
            int oc = i & 63, ic = i >> 6;
            float v = TRANS ? w[(long)(ic0 + ic) * Cout + oct * 64 + oc]
                            : w[(long)(oct * 64 + oc) * Cin + ic0 + ic];
            ws2[i] = pk(v, v);
        }
        __syncthreads();

        for (int ic = 0; ic < ICT; ic++) {
            float4 v = *(const float4*)(in + inb + (long)(ic0 + ic) * HW);
            u64 U0 = pk(v.x, v.y), U1 = pk(v.z, v.w);
            const ulonglong2* wp = (const ulonglong2*)(ws2 + ic * 64 + g * 8);
#pragma unroll
            for (int k = 0; k < 4; k++) {
                ulonglong2 ww = wp[k];
                fma2(acc[2 * k][0], U0, ww.x);     fma2(acc[2 * k][1], U1, ww.x);
                fma2(acc[2 * k + 1][0], U0, ww.y); fma2(acc[2 * k + 1][1], U1, ww.y);
            }
        }
    }

    long ob = ((long)n * Cout + ocb) * HW + hw0;
#pragma unroll
    for (int o = 0; o < 8; o++) {
        float4 v;
        upk(acc[o][0], v.x, v.y);
        upk(acc[o][1], v.z, v.w);
        *(float4*)(out + ob + (long)o * HW) = v;
    }
}

// ---------------------------------------------------------------------------
// Final conv 64 -> 3, k3 s1 p1 (unchanged).
// ---------------------------------------------------------------------------
__global__ void __launch_bounds__(256)
convlast_k(const float* __restrict__ in, const float* __restrict__ w,
           const float* __restrict__ bias, float* __restrict__ out)
{
    __shared__ u64 ws2[64 * 3 * 12];
    int n = blockIdx.y;
    int pxt = blockIdx.x;
    int tid = threadIdx.x;
    int hw0 = pxt * 1024 + tid * 4;
    int oy = hw0 >> 6, ox0 = hw0 & 63;

    for (int i = tid; i < 64 * 3 * 12; i += 256) ws2[i] = 0ull;
    __syncthreads();
    for (int i = tid; i < 64 * 3 * 9; i += 256) {
        int kk = i % 9; int t = i / 9; int oc = t % 3; int ic = t / 3;
        float v = w[((long)oc * 64 + ic) * 9 + kk];
        ws2[((ic * 3 + oc) * 3 + kk / 3) * 4 + kk % 3] = pk(v, v);
    }
    __syncthreads();

    u64 acc[3][2];
#pragma unroll
    for (int o = 0; o < 3; o++) {
        float b = bias[o];
        acc[o][0] = pk(b, b);
        acc[o][1] = pk(b, b);
    }

    const float* ib = in + (long)n * 64 * 4096;
    for (int ic = 0; ic < 64; ic++) {
        const float* ibc = ib + (long)ic * 4096;
#pragma unroll
        for (int ky = 0; ky < 3; ky++) {
            int iy = oy - 1 + ky;
            bool yv = (unsigned)iy < 64u;
            const float* rp = ibc + iy * 64;
            float u[6];
#pragma unroll
            for (int t = 0; t < 6; t++) {
                int x = ox0 - 1 + t;
                u[t] = (yv && (unsigned)x < 64u) ? rp[x] : 0.f;
            }
            u64 U0[3], U1[3];
#pragma unroll
            for (int kx = 0; kx < 3; kx++) {
                U0[kx] = pk(u[kx], u[kx + 1]);
                U1[kx] = pk(u[kx + 2], u[kx + 3]);
            }
#pragma unroll
            for (int o = 0; o < 3; o++) {
                const u64* wb = ws2 + ((ic * 3 + o) * 3 + ky) * 4;
                ulonglong2 w01 = ((const ulonglong2*)wb)[0];
                u64 w2 = wb[2];
                fma2(acc[o][0], U0[0], w01.x); fma2(acc[o][1], U1[0], w01.x);
                fma2(acc[o][0], U0[1], w01.y); fma2(acc[o][1], U1[1], w01.y);
                fma2(acc[o][0], U0[2], w2);    fma2(acc[o][1], U1[2], w2);
            }
        }
    }

#pragma unroll
    for (int o = 0; o < 3; o++) {
        float4 v;
        upk(acc[o][0], v.x, v.y);
        upk(acc[o][1], v.z, v.w);
        *(float4*)(out + ((long)n * 3 + o) * 4096 + hw0) = v;
    }
}

// ---------------------------------------------------------------------------
// BatchNorm stats (unchanged — bit-identical scale/shift).
// ---------------------------------------------------------------------------
__global__ void bn_stats_k(const float* __restrict__ x, const float* __restrict__ g,
                           const float* __restrict__ be, float* __restrict__ scale,
                           float* __restrict__ shift, int C, int N, int HW)
{
    int c = blockIdx.x;
    int tid = threadIdx.x;
    float s = 0.f, ss = 0.f;
    for (int n = 0; n < N; n++) {
        const float* p = x + ((long)(n * C + c)) * HW;
        for (int r = tid; r < HW; r += blockDim.x) {
            float v = p[r];
            s += v; ss += v * v;
        }
    }
    __shared__ float sh1[1024];
    __shared__ float sh2[1024];
    sh1[tid] = s; sh2[tid] = ss;
    __syncthreads();
    for (int ofs = blockDim.x >> 1; ofs > 0; ofs >>= 1) {
        if (tid < ofs) { sh1[tid] += sh1[tid + ofs]; sh2[tid] += sh2[tid + ofs]; }
        __syncthreads();
    }
    if (tid == 0) {
        float cnt = (float)N * (float)HW;
        float m = sh1[0] / cnt;
        float var = sh2[0] / cnt - m * m;
        float sc = g[c] * rsqrtf(var + 1e-5f);
        scale[c] = sc;
        shift[c] = be[c] - m * sc;
    }
}

__global__ void bn_apply4_k(float4* __restrict__ x, const float* __restrict__ scale,
                            const float* __restrict__ shift, int C, int hwsh, int total4)
{
    int i = blockIdx.x * blockDim.x + threadIdx.x;
    if (i >= total4) return;
    int c = (i >> hwsh) % C;
    float s = scale[c], t = shift[c];
    float4 v = x[i];
    v.x = fmaxf(fmaf(v.x, s, t), 0.f);
    v.y = fmaxf(fmaf(v.y, s, t), 0.f);
    v.z = fmaxf(fmaf(v.z, s, t), 0.f);
    v.w = fmaxf(fmaf(v.w, s, t), 0.f);
    x[i] = v;
}

__global__ void cc_k(const float* __restrict__ cb, float* __restrict__ cc)
{
    int j = blockIdx.x * blockDim.x + threadIdx.x;
    if (j >= 256) return;
    double s = 0.0;
    const float* row = cb + (long)j * 256;
    for (int d = 0; d < 256; d++) {
        double v = (double)row[d];
        s += v * v;
    }
    cc[j] = (float)s;
}

// ---------------------------------------------------------------------------
// VQ with reference-exact fp32 distance emulation (unchanged).
// ---------------------------------------------------------------------------
__global__ void vq_exact_k(const float* __restrict__ h, const float* __restrict__ cb,
                           const float* __restrict__ cc, float* __restrict__ hq,
                           float* __restrict__ lossp)
{
    const int POS = 64;
    int b = blockIdx.x >> 2;
    int hw0 = (blockIdx.x & 3) * POS;
    int p = threadIdx.x;

    __shared__ float zs[256 * POS];
    __shared__ float cbs[8 * 256];
    __shared__ float ccs[8];

    const float* hb = h + (long)b * 256 * 256 + hw0;
    for (int d = 0; d < 256; d++)
        zs[d * POS + p] = hb[d * 256 + p];
    __syncthreads();

    float zz = 0.f;
    for (int d = 0; d < 256; d++) {
        float z = zs[d * POS + p];
        zz = fmaf(z, z, zz);
    }

    float best = CUDART_INF_F;
    int bj = 0;

    for (int jc = 0; jc < 256; jc += 8) {
        __syncthreads();
        for (int t = p; t < 8 * 256; t += POS)
            cbs[t] = cb[jc * 256 + t];
        if (p < 8) ccs[p] = cc[jc + p];
        __syncthreads();

        float acc[8];
#pragma unroll
        for (int q = 0; q < 8; q++) acc[q] = 0.f;

        for (int dc = 0; dc < 256; dc += 32) {
            float zreg[32];
#pragma unroll
            for (int d = 0; d < 32; d++)
                zreg[d] = zs[(dc + d) * POS + p];
#pragma unroll
            for (int q = 0; q < 8; q++) {
#pragma unroll
                for (int d = 0; d < 32; d++)
                    acc[q] = fmaf(zreg[d], cbs[q * 256 + dc + d], acc[q]);
            }
        }

#pragma unroll
        for (int q = 0; q < 8; q++) {
            float d2 = (zz + ccs[q]) - 2.0f * acc[q];
            if (d2 < best) { best = d2; bj = jc + q; }
        }
    }

    const float* crow = cb + (long)bj * 256;
    float* hqb = hq + (long)b * 256 * 256 + hw0;
    float l = 0.f;
    for (int d = 0; d < 256; d++) {
        float c = crow[d];
        hqb[d * 256 + p] = c;
        float diff = zs[d * POS + p] - c;
        l = fmaf(diff, diff, l);
    }
    lossp[b * 256 + hw0 + p] = l;
}

__global__ void loss_reduce_k(const float* __restrict__ lossp, float* __restrict__ out2)
{
    int tid = threadIdx.x;
    double s = 0.0;
    for (int i = tid; i < 32768; i += 1024) s += (double)lossp[i];
    __shared__ double sh[1024];
    sh[tid] = s;
    __syncthreads();
    for (int ofs = 512; ofs > 0; ofs >>= 1) {
        if (tid < ofs) sh[tid] += sh[tid + ofs];
        __syncthreads();
    }
    if (tid == 0) {
        float m = (float)(sh[0] / 32768.0);
        out2[0] = m;
        out2[1] = m;
    }
}

// ---------------------------------------------------------------------------
static inline int gridFor(int total, int block) { return (total + block - 1) / block; }

extern "C" void kernel_launch(void* const* d_in, const int* in_sizes, int n_in,
                              void* d_out, int out_size)
{
    const float* x        = (const float*)d_in[0];
    const float* codebook = (const float*)d_in[1];
    const float* e_w1 = (const float*)d_in[2];  const float* e_b1 = (const float*)d_in[3];
    const float* e_g1 = (const float*)d_in[4];  const float* e_be1 = (const float*)d_in[5];
    const float* e_w2 = (const float*)d_in[6];  const float* e_b2 = (const float*)d_in[7];
    const float* e_g2 = (const float*)d_in[8];  const float* e_be2 = (const float*)d_in[9];
    const float* e_w3 = (const float*)d_in[10]; const float* e_b3 = (const float*)d_in[11];
    const float* e_g3 = (const float*)d_in[12]; const float* e_be3 = (const float*)d_in[13];
    const float* e_w4 = (const float*)d_in[14]; const float* e_b4 = (const float*)d_in[15];
    const float* d_w1 = (const float*)d_in[16]; const float* d_b1 = (const float*)d_in[17];
    const float* d_g1 = (const float*)d_in[18]; const float* d_be1 = (const float*)d_in[19];
    const float* d_w2 = (const float*)d_in[20]; const float* d_b2 = (const float*)d_in[21];
    const float* d_g2 = (const float*)d_in[22]; const float* d_be2 = (const float*)d_in[23];
    const float* d_w3 = (const float*)d_in[24]; const float* d_b3 = (const float*)d_in[25];
    const float* d_g3 = (const float*)d_in[26]; const float* d_be3 = (const float*)d_in[27];
    const float* d_w4 = (const float*)d_in[28]; const float* d_b4 = (const float*)d_in[29];

    float* out = (float*)d_out;

    float *a1, *a2, *a3, *h4, *hq, *b1, *b2, *b3, *scale, *shift, *lossp, *cc;
    float *wt2, *wt3, *wtd2, *wtd3;
    cudaGetSymbolAddress((void**)&a1, g_a1);
    cudaGetSymbolAddress((void**)&a2, g_a2);
    cudaGetSymbolAddress((void**)&a3, g_a3);
    cudaGetSymbolAddress((void**)&h4, g_h4);
    cudaGetSymbolAddress((void**)&hq, g_hq);
    cudaGetSymbolAddress((void**)&b1, g_d1);
    cudaGetSymbolAddress((void**)&b2, g_d2);
    cudaGetSymbolAddress((void**)&b3, g_d3);
    cudaGetSymbolAddress((void**)&scale, g_scale);
    cudaGetSymbolAddress((void**)&shift, g_shift);
    cudaGetSymbolAddress((void**)&lossp, g_lossp);
    cudaGetSymbolAddress((void**)&cc, g_cc);
    cudaGetSymbolAddress((void**)&wt2, g_wt2);
    cudaGetSymbolAddress((void**)&wt3, g_wt3);
    cudaGetSymbolAddress((void**)&wtd2, g_wtd2);
    cudaGetSymbolAddress((void**)&wtd3, g_wtd3);

    const int N = 128;

    // dynamic smem sizes (2 buffers each)
    const int SM_C2 = 2 * (4 * 18 * 66 + 4 * 16 * 64) * 4;   // 70784 B
    const int SM_C3 = 2 * (4 * 18 * 34 + 4 * 16 * 64) * 4;   // 52352 B
    const int SM_D2 = 2 * (8 * 18 * 18 + 8 * 4 * 64) * 4;    // 37120 B
    const int SM_D3 = 2 * (8 * 10 * 34 + 8 * 4 * 64) * 4;    // 38144 B
    cudaFuncSetAttribute(convf3_k<32, 8, 4>, cudaFuncAttributeMaxDynamicSharedMemorySize, SM_C2);
    cudaFuncSetAttribute(convf3_k<16, 8, 4>, cudaFuncAttributeMaxDynamicSharedMemorySize, SM_C3);
    cudaFuncSetAttribute(convt3_k<16, 16, 8>, cudaFuncAttributeMaxDynamicSharedMemorySize, SM_D2);
    cudaFuncSetAttribute(convt3_k<32, 8, 8>, cudaFuncAttributeMaxDynamicSharedMemorySize, SM_D3);

    // weight transposes (tap-major for cp.async staging)
    wtr_fwd_k<<<gridFor(64 * 128 * 16, 256), 256>>>(e_w2, wt2, 64, 128);
    wtr_fwd_k<<<gridFor(128 * 192 * 16, 256), 256>>>(e_w3, wt3, 128, 192);
    wtr_tr_k<<<gridFor(192 * 128 * 16, 256), 256>>>(d_w2, wtd2, 192, 128);
    wtr_tr_k<<<gridFor(128 * 64 * 16, 256), 256>>>(d_w3, wtd3, 128, 64);

    // ---- encoder ----
    convf_k<3, 1, 1, 3><<<dim3(32, N), 256>>>(x, e_w1, e_b1, a1,
                                              3, 64, 64, 64, 64, 64, 6, 32);
    bn_stats_k<<<64, 1024>>>(a1, e_g1, e_be1, scale, shift, 64, N, 4096);
    bn_apply4_k<<<gridFor(N * 64 * 1024, 256), 256>>>((float4*)a1, scale, shift, 64, 10,
                                                      N * 64 * 1024);

    convf3_k<32, 8, 4><<<dim3(4 * 2, N), 256, SM_C2>>>(a1, wt2, e_b2, a2, 64, 128, 4);
    bn_stats_k<<<128, 1024>>>(a2, e_g2, e_be2, scale, shift, 128, N, 1024);
    bn_apply4_k<<<gridFor(N * 128 * 256, 256), 256>>>((float4*)a2, scale, shift, 128, 8,
                                                      N * 128 * 256);

    convf3_k<16, 8, 4><<<dim3(2 * 3, N), 256, SM_C3>>>(a2, wt3, e_b3, a3, 128, 192, 2);
    bn_stats_k<<<192, 1024>>>(a3, e_g3, e_be3, scale, shift, 192, N, 256);
    bn_apply4_k<<<gridFor(N * 192 * 64, 256), 256>>>((float4*)a3, scale, shift, 192, 6,
                                                     N * 192 * 64);

    gemm1x1_k<32, false><<<dim3(2 * 4, N), 256>>>(a3, e_w4, e_b4, h4, 192, 256, 256, 2);

    // ---- vector quantization ----
    cc_k<<<1, 256>>>(codebook, cc);
    vq_exact_k<<<512, 64>>>(h4, codebook, cc, hq, lossp);
    loss_reduce_k<<<1, 1024>>>(lossp, out + (out_size - 2));

    // ---- decoder ----
    gemm1x1_k<32, true><<<dim3(2 * 3, N), 256>>>(hq, d_w1, d_b1, b1, 256, 256, 192, 2);
    bn_stats_k<<<192, 1024>>>(b1, d_g1, d_be1, scale, shift, 192, N, 256);
    bn_apply4_k<<<gridFor(N * 192 * 64, 256), 256>>>((float4*)b1, scale, shift, 192, 6,
                                                     N * 192 * 64);

    convt3_k<16, 16, 8><<<dim3(1 * 2, N, 4), 256, SM_D2>>>(b1, wtd2, d_b2, b2, 192, 128, 1);
    bn_stats_k<<<128, 1024>>>(b2, d_g2, d_be2, scale, shift, 128, N, 1024);
    bn_apply4_k<<<gridFor(N * 128 * 256, 256), 256>>>((float4*)b2, scale, shift, 128, 8,
                                                      N * 128 * 256);

    convt3_k<32, 8, 8><<<dim3(4 * 1, N, 4), 256, SM_D3>>>(b2, wtd3, d_b3, b3, 128, 64, 4);
    bn_stats_k<<<64, 1024>>>(b3, d_g3, d_be3, scale, shift, 64, N, 4096);
    bn_apply4_k<<<gridFor(N * 64 * 1024, 256), 256>>>((float4*)b3, scale, shift, 64, 10,
                                                      N * 64 * 1024);

    convlast_k<<<dim3(4, N), 256>>>(b3, d_w4, d_b4, out);
}